// round 11
// baseline (speedup 1.0000x reference)
#include <cuda_runtime.h>
#include <cuda_bf16.h>
#include <cstdint>

// ---------------------------------------------------------------------------
// Problem constants
// ---------------------------------------------------------------------------
#define Bq 2
#define Tt 2048
#define Dd 1024
#define DCc 512
#define DMm 1536
#define Hh 16
#define DEe 4096
#define DGg 1024
#define Mrows (Bq * Tt)          // 4096
#define CHD (DCc / Hh)           // 32
#define MHD (DMm / Hh)           // 96

// ---------------------------------------------------------------------------
// Scratch (device globals; cudaMalloc is forbidden)
// ---------------------------------------------------------------------------
__device__ float g_x1[Mrows * Dd];
__device__ float g_q [Mrows * DCc];
__device__ float g_k [Mrows * DCc];
__device__ float g_v [Mrows * DMm];
__device__ float g_y [Mrows * DMm];
__device__ float g_xa[Mrows * Dd];
__device__ float g_x2[Mrows * Dd];
__device__ float g_e [Mrows * DEe];
__device__ float g_sg[Mrows * DGg];

// ---------------------------------------------------------------------------
// helpers
// ---------------------------------------------------------------------------
__device__ __forceinline__ void mma_tf32(float* c, const uint32_t* a, const uint32_t* b) {
    asm volatile(
        "mma.sync.aligned.m16n8k8.row.col.f32.tf32.tf32.f32 "
        "{%0,%1,%2,%3}, {%4,%5,%6,%7}, {%8,%9}, {%0,%1,%2,%3};"
        : "+f"(c[0]), "+f"(c[1]), "+f"(c[2]), "+f"(c[3])
        : "r"(a[0]), "r"(a[1]), "r"(a[2]), "r"(a[3]), "r"(b[0]), "r"(b[1]));
}

__device__ __forceinline__ void cp_async16(void* smem, const void* gmem) {
    uint32_t s = (uint32_t)__cvta_generic_to_shared(smem);
    asm volatile("cp.async.cg.shared.global [%0], [%1], 16;" :: "r"(s), "l"(gmem));
}
__device__ __forceinline__ void cp_commit() {
    asm volatile("cp.async.commit_group;");
}
template <int N>
__device__ __forceinline__ void cp_wait() {
    asm volatile("cp.async.wait_group %0;" :: "n"(N));
}

// ---------------------------------------------------------------------------
// LayerNorm (unchanged)
// ---------------------------------------------------------------------------
__global__ __launch_bounds__(256) void ln_kernel(
    const float* __restrict__ x, const float* __restrict__ w,
    const float* __restrict__ b, float* __restrict__ out)
{
    int row = blockIdx.x;
    int tid = threadIdx.x;
    const float* xr = x + (size_t)row * Dd;
    float4 v = *(const float4*)(xr + tid * 4);
    float s  = v.x + v.y + v.z + v.w;
    float sq = v.x*v.x + v.y*v.y + v.z*v.z + v.w*v.w;
    #pragma unroll
    for (int o = 16; o > 0; o >>= 1) {
        s  += __shfl_xor_sync(0xffffffffu, s,  o);
        sq += __shfl_xor_sync(0xffffffffu, sq, o);
    }
    __shared__ float ss[8], ssq[8];
    int wid = tid >> 5, lid = tid & 31;
    if (lid == 0) { ss[wid] = s; ssq[wid] = sq; }
    __syncthreads();
    s = 0.f; sq = 0.f;
    #pragma unroll
    for (int i = 0; i < 8; i++) { s += ss[i]; sq += ssq[i]; }
    float mu  = s * (1.f / Dd);
    float var = sq * (1.f / Dd) - mu * mu;
    float rs  = rsqrtf(var + 1e-5f);
    float4 wv = *(const float4*)(w + tid * 4);
    float4 bv = *(const float4*)(b + tid * 4);
    float4 o;
    o.x = (v.x - mu) * rs * wv.x + bv.x;
    o.y = (v.y - mu) * rs * wv.y + bv.y;
    o.z = (v.z - mu) * rs * wv.z + bv.z;
    o.w = (v.w - mu) * rs * wv.w + bv.w;
    *(float4*)(out + (size_t)row * Dd + tid * 4) = o;
}

// ---------------------------------------------------------------------------
// TF32 tensor-core GEMM with cp.async 3-stage pipeline (round-7 proven).
// C = A[M,K] @ W[K,N] + bias; modes: 0 bias, 1 +res, 2 SiLU, 3 sigmoid,
//                                    4 fused: C = silu(res * sigmoid(acc+bias))
// 128x128x16 tile, 256 threads. fp32 fed to HMMA.TF32 (HW truncates mantissa).
// ---------------------------------------------------------------------------
#define AST 20
#define BST 136
#define NSTG 3

__global__ __launch_bounds__(256) void tgemm_kernel(
    const float* __restrict__ A, const float* __restrict__ W,
    const float* __restrict__ bias, const float* __restrict__ res,
    float* __restrict__ C, int M, int N, int K, int mode)
{
    __shared__ float As[NSTG][128][AST];
    __shared__ float Bs[NSTG][16][BST];

    int t = threadIdx.x;
    int bm = blockIdx.y * 128;
    int bn = blockIdx.x * 128;
    int lane = t & 31, wid = t >> 5;
    int r = lane >> 2, q = lane & 3;
    int m_base = (wid & 3) * 32;
    int n_base = (wid >> 2) * 64;

    int a_row0 = t >> 2;           // 0..63 (+64 for second chunk)
    int a_kc   = (t & 3) * 4;
    int b_row0 = t >> 5;           // 0..7 (+8 for second chunk)
    int b_col  = (t & 31) * 4;

    const int nk = K / 16;

    const float* Abase = A + (size_t)(bm + a_row0) * K + a_kc;
    const float* Abase2 = Abase + (size_t)64 * K;
    const float* Wbase = W + (size_t)b_row0 * N + bn + b_col;
    const float* Wbase2 = Wbase + (size_t)8 * N;

    float acc[2][8][4];
    #pragma unroll
    for (int i = 0; i < 2; i++)
        #pragma unroll
        for (int j = 0; j < 8; j++)
            #pragma unroll
            for (int c = 0; c < 4; c++) acc[i][j][c] = 0.f;

    // prologue: issue stages 0,1
    #pragma unroll
    for (int s = 0; s < 2; s++) {
        int k0 = s * 16;
        cp_async16(&As[s][a_row0     ][a_kc], Abase  + k0);
        cp_async16(&As[s][a_row0 + 64][a_kc], Abase2 + k0);
        cp_async16(&Bs[s][b_row0     ][b_col], Wbase  + (size_t)k0 * N);
        cp_async16(&Bs[s][b_row0 + 8 ][b_col], Wbase2 + (size_t)k0 * N);
        cp_commit();
    }
    cp_wait<1>();
    __syncthreads();

    for (int kt = 0; kt < nk; kt++) {
        int buf = kt % NSTG;

        #pragma unroll
        for (int k8 = 0; k8 < 16; k8 += 8) {
            uint32_t a[2][4], b[8][2];
            #pragma unroll
            for (int mt = 0; mt < 2; mt++) {
                int m0 = m_base + mt * 16;
                a[mt][0] = __float_as_uint(As[buf][m0 + r    ][k8 + q]);
                a[mt][1] = __float_as_uint(As[buf][m0 + r + 8][k8 + q]);
                a[mt][2] = __float_as_uint(As[buf][m0 + r    ][k8 + q + 4]);
                a[mt][3] = __float_as_uint(As[buf][m0 + r + 8][k8 + q + 4]);
            }
            #pragma unroll
            for (int nt = 0; nt < 8; nt++) {
                int n0 = n_base + nt * 8;
                b[nt][0] = __float_as_uint(Bs[buf][k8 + q    ][n0 + r]);
                b[nt][1] = __float_as_uint(Bs[buf][k8 + q + 4][n0 + r]);
            }
            #pragma unroll
            for (int mt = 0; mt < 2; mt++)
                #pragma unroll
                for (int nt = 0; nt < 8; nt++)
                    mma_tf32(acc[mt][nt], a[mt], b[nt]);
        }

        // issue stage kt+2
        if (kt + 2 < nk) {
            int s  = (kt + 2) % NSTG;
            int k0 = (kt + 2) * 16;
            cp_async16(&As[s][a_row0     ][a_kc], Abase  + k0);
            cp_async16(&As[s][a_row0 + 64][a_kc], Abase2 + k0);
            cp_async16(&Bs[s][b_row0     ][b_col], Wbase  + (size_t)k0 * N);
            cp_async16(&Bs[s][b_row0 + 8 ][b_col], Wbase2 + (size_t)k0 * N);
        }
        cp_commit();
        cp_wait<1>();
        __syncthreads();
    }

    // epilogue
    #pragma unroll
    for (int mt = 0; mt < 2; mt++) {
        int row0 = bm + m_base + mt * 16 + r;
        #pragma unroll
        for (int nt = 0; nt < 8; nt++) {
            int col = bn + n_base + nt * 8 + q * 2;
            float b0 = bias[col], b1 = bias[col + 1];
            float v0 = acc[mt][nt][0] + b0;
            float v1 = acc[mt][nt][1] + b1;
            float v2 = acc[mt][nt][2] + b0;
            float v3 = acc[mt][nt][3] + b1;
            if (mode == 1) {
                v0 += res[(size_t)row0 * N + col];
                v1 += res[(size_t)row0 * N + col + 1];
                v2 += res[(size_t)(row0 + 8) * N + col];
                v3 += res[(size_t)(row0 + 8) * N + col + 1];
            } else if (mode == 2) {
                v0 = v0 / (1.f + __expf(-v0));
                v1 = v1 / (1.f + __expf(-v1));
                v2 = v2 / (1.f + __expf(-v2));
                v3 = v3 / (1.f + __expf(-v3));
            } else if (mode == 3) {
                v0 = 1.f / (1.f + __expf(-v0));
                v1 = 1.f / (1.f + __expf(-v1));
                v2 = 1.f / (1.f + __expf(-v2));
                v3 = 1.f / (1.f + __expf(-v3));
            } else if (mode == 4) {
                // C = silu(res * sigmoid(acc + bias))
                float e0 = res[(size_t)row0 * N + col];
                float e1 = res[(size_t)row0 * N + col + 1];
                float e2 = res[(size_t)(row0 + 8) * N + col];
                float e3 = res[(size_t)(row0 + 8) * N + col + 1];
                float t0 = e0 * (1.f / (1.f + __expf(-v0)));
                float t1 = e1 * (1.f / (1.f + __expf(-v1)));
                float t2 = e2 * (1.f / (1.f + __expf(-v2)));
                float t3 = e3 * (1.f / (1.f + __expf(-v3)));
                v0 = t0 / (1.f + __expf(-t0));
                v1 = t1 / (1.f + __expf(-t1));
                v2 = t2 / (1.f + __expf(-t2));
                v3 = t3 / (1.f + __expf(-t3));
            }
            *(float2*)(C + (size_t)row0 * N + col)       = make_float2(v0, v1);
            *(float2*)(C + (size_t)(row0 + 8) * N + col) = make_float2(v2, v3);
        }
    }
}

// ---------------------------------------------------------------------------
// TF32 MMA flash attention (cvt-free, validated rounds 8-10)
// ---------------------------------------------------------------------------
#define AT_KST 36
#define AT_VST 68
#define AT_SST 68
#define ATTN_SMEM ((64*AT_KST + 96*AT_VST + 4*16*AT_SST) * 4)

__global__ __launch_bounds__(128) void attn_mma_kernel(
    const float* __restrict__ q, const float* __restrict__ k,
    const float* __restrict__ v, float* __restrict__ y)
{
    extern __shared__ float sm[];
    float* Ks = sm;
    float* Vs = Ks + 64 * AT_KST;
    float* Ss = Vs + 96 * AT_VST;

    int tid  = threadIdx.x;
    int wid  = tid >> 5, lane = tid & 31;
    int r    = lane >> 2, qd = lane & 3;
    int qt   = blockIdx.x;
    int bh   = blockIdx.y;
    int b    = bh >> 4, h = bh & 15;
    int q0   = qt * 64;
    int mrow = wid * 16;

    const float* qbase = q + (size_t)b * Tt * DCc + h * CHD;
    const float* kbase = k + (size_t)b * Tt * DCc + h * CHD;
    const float* vbase = v + (size_t)b * Tt * DMm + h * MHD;

    const float scale = 0.17677669529663687f;
    int grow0 = q0 + mrow + r;
    uint32_t qa[4][4];
    #pragma unroll
    for (int ks = 0; ks < 4; ks++) {
        qa[ks][0] = __float_as_uint(qbase[(size_t)grow0       * DCc + ks * 8 + qd    ] * scale);
        qa[ks][1] = __float_as_uint(qbase[(size_t)(grow0 + 8) * DCc + ks * 8 + qd    ] * scale);
        qa[ks][2] = __float_as_uint(qbase[(size_t)grow0       * DCc + ks * 8 + qd + 4] * scale);
        qa[ks][3] = __float_as_uint(qbase[(size_t)(grow0 + 8) * DCc + ks * 8 + qd + 4] * scale);
    }

    float m0 = -1e30f, m1 = -1e30f, l0 = 0.f, l1 = 0.f;
    float o[12][4];
    #pragma unroll
    for (int nt = 0; nt < 12; nt++)
        #pragma unroll
        for (int c = 0; c < 4; c++) o[nt][c] = 0.f;

    float* Sw = Ss + wid * 16 * AT_SST;

    for (int j = 0; j <= qt; j++) {
        int k0 = j * 64;
        __syncthreads();
        {
            int row = tid >> 1;
            int c0  = (tid & 1) * 16;
            const float* src = kbase + (size_t)(k0 + row) * DCc + c0;
            float* dst = &Ks[row * AT_KST + c0];
            #pragma unroll
            for (int jj = 0; jj < 4; jj++) {
                float4 f = *(const float4*)(src + jj * 4);
                *(float4*)(dst + jj * 4) = f;
            }
        }
        {
            #pragma unroll
            for (int it = 0; it < 12; it++) {
                int idx  = it * 128 + tid;
                int trow = idx / 24, c4 = idx % 24;
                float4 f = *(const float4*)(vbase + (size_t)(k0 + trow) * DMm + c4 * 4);
                Vs[(c4 * 4 + 0) * AT_VST + trow] = f.x;
                Vs[(c4 * 4 + 1) * AT_VST + trow] = f.y;
                Vs[(c4 * 4 + 2) * AT_VST + trow] = f.z;
                Vs[(c4 * 4 + 3) * AT_VST + trow] = f.w;
            }
        }
        __syncthreads();

        float sc[8][4];
        #pragma unroll
        for (int nt = 0; nt < 8; nt++)
            #pragma unroll
            for (int c = 0; c < 4; c++) sc[nt][c] = 0.f;
        #pragma unroll
        for (int ks = 0; ks < 4; ks++) {
            #pragma unroll
            for (int nt = 0; nt < 8; nt++) {
                uint32_t bb[2];
                bb[0] = __float_as_uint(Ks[(nt * 8 + r) * AT_KST + ks * 8 + qd    ]);
                bb[1] = __float_as_uint(Ks[(nt * 8 + r) * AT_KST + ks * 8 + qd + 4]);
                mma_tf32(sc[nt], qa[ks], bb);
            }
        }

        float mx0 = -1e30f, mx1 = -1e30f;
        #pragma unroll
        for (int nt = 0; nt < 8; nt++) {
            int c = k0 + nt * 8 + 2 * qd;
            if (c     > grow0    ) sc[nt][0] = -1e30f;
            if (c + 1 > grow0    ) sc[nt][1] = -1e30f;
            if (c     > grow0 + 8) sc[nt][2] = -1e30f;
            if (c + 1 > grow0 + 8) sc[nt][3] = -1e30f;
            mx0 = fmaxf(mx0, fmaxf(sc[nt][0], sc[nt][1]));
            mx1 = fmaxf(mx1, fmaxf(sc[nt][2], sc[nt][3]));
        }
        mx0 = fmaxf(mx0, __shfl_xor_sync(0xffffffffu, mx0, 1));
        mx0 = fmaxf(mx0, __shfl_xor_sync(0xffffffffu, mx0, 2));
        mx1 = fmaxf(mx1, __shfl_xor_sync(0xffffffffu, mx1, 1));
        mx1 = fmaxf(mx1, __shfl_xor_sync(0xffffffffu, mx1, 2));

        float mn0 = fmaxf(m0, mx0), mn1 = fmaxf(m1, mx1);
        float corr0 = __expf(m0 - mn0), corr1 = __expf(m1 - mn1);
        float s0 = 0.f, s1 = 0.f;
        #pragma unroll
        for (int nt = 0; nt < 8; nt++) {
            float p00 = __expf(sc[nt][0] - mn0);
            float p01 = __expf(sc[nt][1] - mn0);
            float p10 = __expf(sc[nt][2] - mn1);
            float p11 = __expf(sc[nt][3] - mn1);
            s0 += p00 + p01;
            s1 += p10 + p11;
            int cb = nt * 8 + 2 * qd;
            Sw[r * AT_SST + cb]           = p00;
            Sw[r * AT_SST + cb + 1]       = p01;
            Sw[(r + 8) * AT_SST + cb]     = p10;
            Sw[(r + 8) * AT_SST + cb + 1] = p11;
        }
        s0 += __shfl_xor_sync(0xffffffffu, s0, 1);
        s0 += __shfl_xor_sync(0xffffffffu, s0, 2);
        s1 += __shfl_xor_sync(0xffffffffu, s1, 1);
        s1 += __shfl_xor_sync(0xffffffffu, s1, 2);
        l0 = l0 * corr0 + s0;
        l1 = l1 * corr1 + s1;
        m0 = mn0; m1 = mn1;
        #pragma unroll
        for (int nt = 0; nt < 12; nt++) {
            o[nt][0] *= corr0; o[nt][1] *= corr0;
            o[nt][2] *= corr1; o[nt][3] *= corr1;
        }
        __syncwarp();

        #pragma unroll
        for (int ks = 0; ks < 8; ks++) {
            uint32_t pa[4];
            pa[0] = __float_as_uint(Sw[r       * AT_SST + ks * 8 + qd    ]);
            pa[1] = __float_as_uint(Sw[(r + 8) * AT_SST + ks * 8 + qd    ]);
            pa[2] = __float_as_uint(Sw[r       * AT_SST + ks * 8 + qd + 4]);
            pa[3] = __float_as_uint(Sw[(r + 8) * AT_SST + ks * 8 + qd + 4]);
            #pragma unroll
            for (int nt = 0; nt < 12; nt++) {
                uint32_t bb[2];
                bb[0] = __float_as_uint(Vs[(nt * 8 + r) * AT_VST + ks * 8 + qd    ]);
                bb[1] = __float_as_uint(Vs[(nt * 8 + r) * AT_VST + ks * 8 + qd + 4]);
                mma_tf32(o[nt], pa, bb);
            }
        }
        __syncwarp();
    }

    float inv0 = 1.f / l0, inv1 = 1.f / l1;
    float* yb = y + (size_t)b * Tt * DMm + h * MHD;
    #pragma unroll
    for (int nt = 0; nt < 12; nt++) {
        int cb = nt * 8 + 2 * qd;
        *(float2*)(yb + (size_t)grow0 * DMm + cb) =
            make_float2(o[nt][0] * inv0, o[nt][1] * inv0);
        *(float2*)(yb + (size_t)(grow0 + 8) * DMm + cb) =
            make_float2(o[nt][2] * inv1, o[nt][3] * inv1);
    }
}

// ---------------------------------------------------------------------------
// Host launcher
// ---------------------------------------------------------------------------
extern "C" void kernel_launch(void* const* d_in, const int* in_sizes, int n_in,
                              void* d_out, int out_size)
{
    const float* x     = (const float*)d_in[0];
    const float* ln1_w = (const float*)d_in[2];
    const float* ln1_b = (const float*)d_in[3];
    const float* wq    = (const float*)d_in[4];
    const float* bq    = (const float*)d_in[5];
    const float* wk    = (const float*)d_in[6];
    const float* bk    = (const float*)d_in[7];
    const float* wv    = (const float*)d_in[8];
    const float* bv    = (const float*)d_in[9];
    const float* wo    = (const float*)d_in[10];
    const float* bo    = (const float*)d_in[11];
    const float* ln2_w = (const float*)d_in[12];
    const float* ln2_b = (const float*)d_in[13];
    const float* we    = (const float*)d_in[14];
    const float* be    = (const float*)d_in[15];
    const float* wg    = (const float*)d_in[16];
    const float* bg    = (const float*)d_in[17];
    const float* wu    = (const float*)d_in[18];
    const float* bu    = (const float*)d_in[19];
    const float* wc    = (const float*)d_in[20];
    const float* bc    = (const float*)d_in[21];
    float* out = (float*)d_out;

    float *x1, *qp, *kp, *vp, *yp, *xa, *x2, *ep, *sg;
    cudaGetSymbolAddress((void**)&x1, g_x1);
    cudaGetSymbolAddress((void**)&qp, g_q);
    cudaGetSymbolAddress((void**)&kp, g_k);
    cudaGetSymbolAddress((void**)&vp, g_v);
    cudaGetSymbolAddress((void**)&yp, g_y);
    cudaGetSymbolAddress((void**)&xa, g_xa);
    cudaGetSymbolAddress((void**)&x2, g_x2);
    cudaGetSymbolAddress((void**)&ep, g_e);
    cudaGetSymbolAddress((void**)&sg, g_sg);

    cudaFuncSetAttribute(attn_mma_kernel,
                         cudaFuncAttributeMaxDynamicSharedMemorySize, ATTN_SMEM);

    // 1) LN1
    ln_kernel<<<Mrows, 256>>>(x, ln1_w, ln1_b, x1);

    // 2) Q/K/V projections (separate launches — single code path per kernel)
    tgemm_kernel<<<dim3(DCc/128, Mrows/128), 256>>>(x1, wq, bq, nullptr, qp, Mrows, DCc, Dd, 0);
    tgemm_kernel<<<dim3(DCc/128, Mrows/128), 256>>>(x1, wk, bk, nullptr, kp, Mrows, DCc, Dd, 0);
    tgemm_kernel<<<dim3(DMm/128, Mrows/128), 256>>>(x1, wv, bv, nullptr, vp, Mrows, DMm, Dd, 0);

    // 3) causal attention (TF32 MMA)
    attn_mma_kernel<<<dim3(Tt/64, Bq*Hh), 128, ATTN_SMEM>>>(qp, kp, vp, yp);

    // 4) output projection + residual
    tgemm_kernel<<<dim3(Dd/128, Mrows/128), 256>>>(yp, wo, bo, x, xa, Mrows, Dd, DMm, 1);

    // 5) LN2
    ln_kernel<<<Mrows, 256>>>(xa, ln2_w, ln2_b, x2);

    // 6) e = x2@we + be
    tgemm_kernel<<<dim3(DEe/128, Mrows/128), 256>>>(x2, we, be, nullptr, ep, Mrows, DEe, Dd, 0);

    // 7) sg = silu(x2@wg + bg)
    tgemm_kernel<<<dim3(DGg/128, Mrows/128), 256>>>(x2, wg, bg, nullptr, sg, Mrows, DGg, Dd, 2);

    // 8) e = silu(e * sigmoid(sg@wu + bu))   [fused eg epilogue, mode 4]
    tgemm_kernel<<<dim3(DEe/128, Mrows/128), 256>>>(sg, wu, bu, ep, ep, Mrows, DEe, DGg, 4);

    // 9) out = xa + e@wc + bc
    tgemm_kernel<<<dim3(Dd/128, Mrows/128), 256>>>(ep, wc, bc, xa, out, Mrows, Dd, DEe, 1);
}

// round 12
// speedup vs baseline: 1.0257x; 1.0257x over previous
#include <cuda_runtime.h>
#include <cuda_bf16.h>
#include <cstdint>

// ---------------------------------------------------------------------------
// Problem constants
// ---------------------------------------------------------------------------
#define Bq 2
#define Tt 2048
#define Dd 1024
#define DCc 512
#define DMm 1536
#define Hh 16
#define DEe 4096
#define DGg 1024
#define Mrows (Bq * Tt)          // 4096
#define CHD (DCc / Hh)           // 32
#define MHD (DMm / Hh)           // 96

// ---------------------------------------------------------------------------
// Scratch (device globals; cudaMalloc is forbidden)
// ---------------------------------------------------------------------------
__device__ float g_x1[Mrows * Dd];
__device__ float g_q [Mrows * DCc];
__device__ float g_k [Mrows * DCc];
__device__ float g_v [Mrows * DMm];
__device__ float g_y [Mrows * DMm];
__device__ float g_xa[Mrows * Dd];
__device__ float g_x2[Mrows * Dd];
__device__ float g_e [Mrows * DEe];
__device__ float g_sg[Mrows * DGg];

// ---------------------------------------------------------------------------
// helpers
// ---------------------------------------------------------------------------
__device__ __forceinline__ uint32_t f2tf32(float f) {
    uint32_t u;
    asm("cvt.rna.tf32.f32 %0, %1;" : "=r"(u) : "f"(f));
    return u;
}

__device__ __forceinline__ void mma_tf32(float* c, const uint32_t* a, const uint32_t* b) {
    asm volatile(
        "mma.sync.aligned.m16n8k8.row.col.f32.tf32.tf32.f32 "
        "{%0,%1,%2,%3}, {%4,%5,%6,%7}, {%8,%9}, {%0,%1,%2,%3};"
        : "+f"(c[0]), "+f"(c[1]), "+f"(c[2]), "+f"(c[3])
        : "r"(a[0]), "r"(a[1]), "r"(a[2]), "r"(a[3]), "r"(b[0]), "r"(b[1]));
}

__device__ __forceinline__ void cp_async16(void* smem, const void* gmem) {
    uint32_t s = (uint32_t)__cvta_generic_to_shared(smem);
    asm volatile("cp.async.cg.shared.global [%0], [%1], 16;" :: "r"(s), "l"(gmem));
}
__device__ __forceinline__ void cp_commit() {
    asm volatile("cp.async.commit_group;");
}
template <int N>
__device__ __forceinline__ void cp_wait() {
    asm volatile("cp.async.wait_group %0;" :: "n"(N));
}

// ---------------------------------------------------------------------------
// LayerNorm (unchanged)
// ---------------------------------------------------------------------------
__global__ __launch_bounds__(256) void ln_kernel(
    const float* __restrict__ x, const float* __restrict__ w,
    const float* __restrict__ b, float* __restrict__ out)
{
    int row = blockIdx.x;
    int tid = threadIdx.x;
    const float* xr = x + (size_t)row * Dd;
    float4 v = *(const float4*)(xr + tid * 4);
    float s  = v.x + v.y + v.z + v.w;
    float sq = v.x*v.x + v.y*v.y + v.z*v.z + v.w*v.w;
    #pragma unroll
    for (int o = 16; o > 0; o >>= 1) {
        s  += __shfl_xor_sync(0xffffffffu, s,  o);
        sq += __shfl_xor_sync(0xffffffffu, sq, o);
    }
    __shared__ float ss[8], ssq[8];
    int wid = tid >> 5, lid = tid & 31;
    if (lid == 0) { ss[wid] = s; ssq[wid] = sq; }
    __syncthreads();
    s = 0.f; sq = 0.f;
    #pragma unroll
    for (int i = 0; i < 8; i++) { s += ss[i]; sq += ssq[i]; }
    float mu  = s * (1.f / Dd);
    float var = sq * (1.f / Dd) - mu * mu;
    float rs  = rsqrtf(var + 1e-5f);
    float4 wv = *(const float4*)(w + tid * 4);
    float4 bv = *(const float4*)(b + tid * 4);
    float4 o;
    o.x = (v.x - mu) * rs * wv.x + bv.x;
    o.y = (v.y - mu) * rs * wv.y + bv.y;
    o.z = (v.z - mu) * rs * wv.z + bv.z;
    o.w = (v.w - mu) * rs * wv.w + bv.w;
    *(float4*)(out + (size_t)row * Dd + tid * 4) = o;
}

// ---------------------------------------------------------------------------
// TF32 tensor-core GEMM with cp.async 3-stage pipeline (round-7 proven).
// modes: 0 bias, 1 +res, 2 SiLU, 3 sigmoid, 4 fused: C = silu(res*sigmoid(acc+bias))
// 128x128x16 tile, 256 threads. fp32 fed to HMMA.TF32 (HW truncates mantissa).
// ---------------------------------------------------------------------------
#define AST 20
#define BST 136
#define NSTG 3

__global__ __launch_bounds__(256) void tgemm_kernel(
    const float* __restrict__ A, const float* __restrict__ W,
    const float* __restrict__ bias, const float* __restrict__ res,
    float* __restrict__ C, int M, int N, int K, int mode)
{
    __shared__ float As[NSTG][128][AST];
    __shared__ float Bs[NSTG][16][BST];

    int t = threadIdx.x;
    int bm = blockIdx.y * 128;
    int bn = blockIdx.x * 128;
    int lane = t & 31, wid = t >> 5;
    int r = lane >> 2, q = lane & 3;
    int m_base = (wid & 3) * 32;
    int n_base = (wid >> 2) * 64;

    int a_row0 = t >> 2;           // 0..63 (+64 for second chunk)
    int a_kc   = (t & 3) * 4;
    int b_row0 = t >> 5;           // 0..7 (+8 for second chunk)
    int b_col  = (t & 31) * 4;

    const int nk = K / 16;

    const float* Abase = A + (size_t)(bm + a_row0) * K + a_kc;
    const float* Abase2 = Abase + (size_t)64 * K;
    const float* Wbase = W + (size_t)b_row0 * N + bn + b_col;
    const float* Wbase2 = Wbase + (size_t)8 * N;

    float acc[2][8][4];
    #pragma unroll
    for (int i = 0; i < 2; i++)
        #pragma unroll
        for (int j = 0; j < 8; j++)
            #pragma unroll
            for (int c = 0; c < 4; c++) acc[i][j][c] = 0.f;

    // prologue: issue stages 0,1
    #pragma unroll
    for (int s = 0; s < 2; s++) {
        int k0 = s * 16;
        cp_async16(&As[s][a_row0     ][a_kc], Abase  + k0);
        cp_async16(&As[s][a_row0 + 64][a_kc], Abase2 + k0);
        cp_async16(&Bs[s][b_row0     ][b_col], Wbase  + (size_t)k0 * N);
        cp_async16(&Bs[s][b_row0 + 8 ][b_col], Wbase2 + (size_t)k0 * N);
        cp_commit();
    }
    cp_wait<1>();
    __syncthreads();

    for (int kt = 0; kt < nk; kt++) {
        int buf = kt % NSTG;

        #pragma unroll
        for (int k8 = 0; k8 < 16; k8 += 8) {
            uint32_t a[2][4], b[8][2];
            #pragma unroll
            for (int mt = 0; mt < 2; mt++) {
                int m0 = m_base + mt * 16;
                a[mt][0] = __float_as_uint(As[buf][m0 + r    ][k8 + q]);
                a[mt][1] = __float_as_uint(As[buf][m0 + r + 8][k8 + q]);
                a[mt][2] = __float_as_uint(As[buf][m0 + r    ][k8 + q + 4]);
                a[mt][3] = __float_as_uint(As[buf][m0 + r + 8][k8 + q + 4]);
            }
            #pragma unroll
            for (int nt = 0; nt < 8; nt++) {
                int n0 = n_base + nt * 8;
                b[nt][0] = __float_as_uint(Bs[buf][k8 + q    ][n0 + r]);
                b[nt][1] = __float_as_uint(Bs[buf][k8 + q + 4][n0 + r]);
            }
            #pragma unroll
            for (int mt = 0; mt < 2; mt++)
                #pragma unroll
                for (int nt = 0; nt < 8; nt++)
                    mma_tf32(acc[mt][nt], a[mt], b[nt]);
        }

        // issue stage kt+2
        if (kt + 2 < nk) {
            int s  = (kt + 2) % NSTG;
            int k0 = (kt + 2) * 16;
            cp_async16(&As[s][a_row0     ][a_kc], Abase  + k0);
            cp_async16(&As[s][a_row0 + 64][a_kc], Abase2 + k0);
            cp_async16(&Bs[s][b_row0     ][b_col], Wbase  + (size_t)k0 * N);
            cp_async16(&Bs[s][b_row0 + 8 ][b_col], Wbase2 + (size_t)k0 * N);
        }
        cp_commit();
        cp_wait<1>();
        __syncthreads();
    }

    // epilogue
    #pragma unroll
    for (int mt = 0; mt < 2; mt++) {
        int row0 = bm + m_base + mt * 16 + r;
        #pragma unroll
        for (int nt = 0; nt < 8; nt++) {
            int col = bn + n_base + nt * 8 + q * 2;
            float b0 = bias[col], b1 = bias[col + 1];
            float v0 = acc[mt][nt][0] + b0;
            float v1 = acc[mt][nt][1] + b1;
            float v2 = acc[mt][nt][2] + b0;
            float v3 = acc[mt][nt][3] + b1;
            if (mode == 1) {
                v0 += res[(size_t)row0 * N + col];
                v1 += res[(size_t)row0 * N + col + 1];
                v2 += res[(size_t)(row0 + 8) * N + col];
                v3 += res[(size_t)(row0 + 8) * N + col + 1];
            } else if (mode == 2) {
                v0 = v0 / (1.f + __expf(-v0));
                v1 = v1 / (1.f + __expf(-v1));
                v2 = v2 / (1.f + __expf(-v2));
                v3 = v3 / (1.f + __expf(-v3));
            } else if (mode == 3) {
                v0 = 1.f / (1.f + __expf(-v0));
                v1 = 1.f / (1.f + __expf(-v1));
                v2 = 1.f / (1.f + __expf(-v2));
                v3 = 1.f / (1.f + __expf(-v3));
            } else if (mode == 4) {
                // C = silu(res * sigmoid(acc + bias))
                float e0 = res[(size_t)row0 * N + col];
                float e1 = res[(size_t)row0 * N + col + 1];
                float e2 = res[(size_t)(row0 + 8) * N + col];
                float e3 = res[(size_t)(row0 + 8) * N + col + 1];
                float t0 = e0 * (1.f / (1.f + __expf(-v0)));
                float t1 = e1 * (1.f / (1.f + __expf(-v1)));
                float t2 = e2 * (1.f / (1.f + __expf(-v2)));
                float t3 = e3 * (1.f / (1.f + __expf(-v3)));
                v0 = t0 / (1.f + __expf(-t0));
                v1 = t1 / (1.f + __expf(-t1));
                v2 = t2 / (1.f + __expf(-t2));
                v3 = t3 / (1.f + __expf(-t3));
            }
            *(float2*)(C + (size_t)row0 * N + col)       = make_float2(v0, v1);
            *(float2*)(C + (size_t)(row0 + 8) * N + col) = make_float2(v2, v3);
        }
    }
}

// ---------------------------------------------------------------------------
// TF32 MMA flash attention — round-7 version EXACTLY (with f2tf32 round-trip)
// ---------------------------------------------------------------------------
#define AT_KST 36
#define AT_VST 68
#define AT_SST 68
#define ATTN_SMEM ((64*AT_KST + 96*AT_VST + 4*16*AT_SST) * 4)

__global__ __launch_bounds__(128) void attn_mma_kernel(
    const float* __restrict__ q, const float* __restrict__ k,
    const float* __restrict__ v, float* __restrict__ y)
{
    extern __shared__ float sm[];
    float* Ks = sm;
    float* Vs = Ks + 64 * AT_KST;
    float* Ss = Vs + 96 * AT_VST;

    int tid  = threadIdx.x;
    int wid  = tid >> 5, lane = tid & 31;
    int r    = lane >> 2, qd = lane & 3;
    int qt   = blockIdx.x;
    int bh   = blockIdx.y;
    int b    = bh >> 4, h = bh & 15;
    int q0   = qt * 64;
    int mrow = wid * 16;

    const float* qbase = q + (size_t)b * Tt * DCc + h * CHD;
    const float* kbase = k + (size_t)b * Tt * DCc + h * CHD;
    const float* vbase = v + (size_t)b * Tt * DMm + h * MHD;

    const float scale = 0.17677669529663687f;
    int grow0 = q0 + mrow + r;
    uint32_t qa[4][4];
    #pragma unroll
    for (int ks = 0; ks < 4; ks++) {
        qa[ks][0] = f2tf32(qbase[(size_t)grow0       * DCc + ks * 8 + qd    ] * scale);
        qa[ks][1] = f2tf32(qbase[(size_t)(grow0 + 8) * DCc + ks * 8 + qd    ] * scale);
        qa[ks][2] = f2tf32(qbase[(size_t)grow0       * DCc + ks * 8 + qd + 4] * scale);
        qa[ks][3] = f2tf32(qbase[(size_t)(grow0 + 8) * DCc + ks * 8 + qd + 4] * scale);
    }

    float m0 = -1e30f, m1 = -1e30f, l0 = 0.f, l1 = 0.f;
    float o[12][4];
    #pragma unroll
    for (int nt = 0; nt < 12; nt++)
        #pragma unroll
        for (int c = 0; c < 4; c++) o[nt][c] = 0.f;

    float* Sw = Ss + wid * 16 * AT_SST;

    for (int j = 0; j <= qt; j++) {
        int k0 = j * 64;
        __syncthreads();
        {
            int row = tid >> 1;
            int c0  = (tid & 1) * 16;
            const float* src = kbase + (size_t)(k0 + row) * DCc + c0;
            uint32_t* dst = (uint32_t*)&Ks[row * AT_KST + c0];
            #pragma unroll
            for (int jj = 0; jj < 4; jj++) {
                float4 f = *(const float4*)(src + jj * 4);
                uint4 u = make_uint4(f2tf32(f.x), f2tf32(f.y), f2tf32(f.z), f2tf32(f.w));
                *(uint4*)(dst + jj * 4) = u;
            }
        }
        {
            #pragma unroll
            for (int it = 0; it < 12; it++) {
                int idx  = it * 128 + tid;
                int trow = idx / 24, c4 = idx % 24;
                float4 f = *(const float4*)(vbase + (size_t)(k0 + trow) * DMm + c4 * 4);
                Vs[(c4 * 4 + 0) * AT_VST + trow] = __uint_as_float(f2tf32(f.x));
                Vs[(c4 * 4 + 1) * AT_VST + trow] = __uint_as_float(f2tf32(f.y));
                Vs[(c4 * 4 + 2) * AT_VST + trow] = __uint_as_float(f2tf32(f.z));
                Vs[(c4 * 4 + 3) * AT_VST + trow] = __uint_as_float(f2tf32(f.w));
            }
        }
        __syncthreads();

        float sc[8][4];
        #pragma unroll
        for (int nt = 0; nt < 8; nt++)
            #pragma unroll
            for (int c = 0; c < 4; c++) sc[nt][c] = 0.f;
        #pragma unroll
        for (int ks = 0; ks < 4; ks++) {
            #pragma unroll
            for (int nt = 0; nt < 8; nt++) {
                uint32_t bb[2];
                bb[0] = __float_as_uint(Ks[(nt * 8 + r) * AT_KST + ks * 8 + qd    ]);
                bb[1] = __float_as_uint(Ks[(nt * 8 + r) * AT_KST + ks * 8 + qd + 4]);
                mma_tf32(sc[nt], qa[ks], bb);
            }
        }

        float mx0 = -1e30f, mx1 = -1e30f;
        #pragma unroll
        for (int nt = 0; nt < 8; nt++) {
            int c = k0 + nt * 8 + 2 * qd;
            if (c     > grow0    ) sc[nt][0] = -1e30f;
            if (c + 1 > grow0    ) sc[nt][1] = -1e30f;
            if (c     > grow0 + 8) sc[nt][2] = -1e30f;
            if (c + 1 > grow0 + 8) sc[nt][3] = -1e30f;
            mx0 = fmaxf(mx0, fmaxf(sc[nt][0], sc[nt][1]));
            mx1 = fmaxf(mx1, fmaxf(sc[nt][2], sc[nt][3]));
        }
        mx0 = fmaxf(mx0, __shfl_xor_sync(0xffffffffu, mx0, 1));
        mx0 = fmaxf(mx0, __shfl_xor_sync(0xffffffffu, mx0, 2));
        mx1 = fmaxf(mx1, __shfl_xor_sync(0xffffffffu, mx1, 1));
        mx1 = fmaxf(mx1, __shfl_xor_sync(0xffffffffu, mx1, 2));

        float mn0 = fmaxf(m0, mx0), mn1 = fmaxf(m1, mx1);
        float corr0 = __expf(m0 - mn0), corr1 = __expf(m1 - mn1);
        float s0 = 0.f, s1 = 0.f;
        #pragma unroll
        for (int nt = 0; nt < 8; nt++) {
            float p00 = __expf(sc[nt][0] - mn0);
            float p01 = __expf(sc[nt][1] - mn0);
            float p10 = __expf(sc[nt][2] - mn1);
            float p11 = __expf(sc[nt][3] - mn1);
            s0 += p00 + p01;
            s1 += p10 + p11;
            int cb = nt * 8 + 2 * qd;
            Sw[r * AT_SST + cb]           = __uint_as_float(f2tf32(p00));
            Sw[r * AT_SST + cb + 1]       = __uint_as_float(f2tf32(p01));
            Sw[(r + 8) * AT_SST + cb]     = __uint_as_float(f2tf32(p10));
            Sw[(r + 8) * AT_SST + cb + 1] = __uint_as_float(f2tf32(p11));
        }
        s0 += __shfl_xor_sync(0xffffffffu, s0, 1);
        s0 += __shfl_xor_sync(0xffffffffu, s0, 2);
        s1 += __shfl_xor_sync(0xffffffffu, s1, 1);
        s1 += __shfl_xor_sync(0xffffffffu, s1, 2);
        l0 = l0 * corr0 + s0;
        l1 = l1 * corr1 + s1;
        m0 = mn0; m1 = mn1;
        #pragma unroll
        for (int nt = 0; nt < 12; nt++) {
            o[nt][0] *= corr0; o[nt][1] *= corr0;
            o[nt][2] *= corr1; o[nt][3] *= corr1;
        }
        __syncwarp();

        #pragma unroll
        for (int ks = 0; ks < 8; ks++) {
            uint32_t pa[4];
            pa[0] = __float_as_uint(Sw[r       * AT_SST + ks * 8 + qd    ]);
            pa[1] = __float_as_uint(Sw[(r + 8) * AT_SST + ks * 8 + qd    ]);
            pa[2] = __float_as_uint(Sw[r       * AT_SST + ks * 8 + qd + 4]);
            pa[3] = __float_as_uint(Sw[(r + 8) * AT_SST + ks * 8 + qd + 4]);
            #pragma unroll
            for (int nt = 0; nt < 12; nt++) {
                uint32_t bb[2];
                bb[0] = __float_as_uint(Vs[(nt * 8 + r) * AT_VST + ks * 8 + qd    ]);
                bb[1] = __float_as_uint(Vs[(nt * 8 + r) * AT_VST + ks * 8 + qd + 4]);
                mma_tf32(o[nt], pa, bb);
            }
        }
        __syncwarp();
    }

    float inv0 = 1.f / l0, inv1 = 1.f / l1;
    float* yb = y + (size_t)b * Tt * DMm + h * MHD;
    #pragma unroll
    for (int nt = 0; nt < 12; nt++) {
        int cb = nt * 8 + 2 * qd;
        *(float2*)(yb + (size_t)grow0 * DMm + cb) =
            make_float2(o[nt][0] * inv0, o[nt][1] * inv0);
        *(float2*)(yb + (size_t)(grow0 + 8) * DMm + cb) =
            make_float2(o[nt][2] * inv1, o[nt][3] * inv1);
    }
}

// ---------------------------------------------------------------------------
// Host launcher
// ---------------------------------------------------------------------------
extern "C" void kernel_launch(void* const* d_in, const int* in_sizes, int n_in,
                              void* d_out, int out_size)
{
    const float* x     = (const float*)d_in[0];
    const float* ln1_w = (const float*)d_in[2];
    const float* ln1_b = (const float*)d_in[3];
    const float* wq    = (const float*)d_in[4];
    const float* bq    = (const float*)d_in[5];
    const float* wk    = (const float*)d_in[6];
    const float* bk    = (const float*)d_in[7];
    const float* wv    = (const float*)d_in[8];
    const float* bv    = (const float*)d_in[9];
    const float* wo    = (const float*)d_in[10];
    const float* bo    = (const float*)d_in[11];
    const float* ln2_w = (const float*)d_in[12];
    const float* ln2_b = (const float*)d_in[13];
    const float* we    = (const float*)d_in[14];
    const float* be    = (const float*)d_in[15];
    const float* wg    = (const float*)d_in[16];
    const float* bg    = (const float*)d_in[17];
    const float* wu    = (const float*)d_in[18];
    const float* bu    = (const float*)d_in[19];
    const float* wc    = (const float*)d_in[20];
    const float* bc    = (const float*)d_in[21];
    float* out = (float*)d_out;

    float *x1, *qp, *kp, *vp, *yp, *xa, *x2, *ep, *sg;
    cudaGetSymbolAddress((void**)&x1, g_x1);
    cudaGetSymbolAddress((void**)&qp, g_q);
    cudaGetSymbolAddress((void**)&kp, g_k);
    cudaGetSymbolAddress((void**)&vp, g_v);
    cudaGetSymbolAddress((void**)&yp, g_y);
    cudaGetSymbolAddress((void**)&xa, g_xa);
    cudaGetSymbolAddress((void**)&x2, g_x2);
    cudaGetSymbolAddress((void**)&ep, g_e);
    cudaGetSymbolAddress((void**)&sg, g_sg);

    cudaFuncSetAttribute(attn_mma_kernel,
                         cudaFuncAttributeMaxDynamicSharedMemorySize, ATTN_SMEM);

    // 1) LN1
    ln_kernel<<<Mrows, 256>>>(x, ln1_w, ln1_b, x1);

    // 2) Q/K/V projections
    tgemm_kernel<<<dim3(DCc/128, Mrows/128), 256>>>(x1, wq, bq, nullptr, qp, Mrows, DCc, Dd, 0);
    tgemm_kernel<<<dim3(DCc/128, Mrows/128), 256>>>(x1, wk, bk, nullptr, kp, Mrows, DCc, Dd, 0);
    tgemm_kernel<<<dim3(DMm/128, Mrows/128), 256>>>(x1, wv, bv, nullptr, vp, Mrows, DMm, Dd, 0);

    // 3) causal attention (TF32 MMA, round-7 version)
    attn_mma_kernel<<<dim3(Tt/64, Bq*Hh), 128, ATTN_SMEM>>>(qp, kp, vp, yp);

    // 4) output projection + residual
    tgemm_kernel<<<dim3(Dd/128, Mrows/128), 256>>>(yp, wo, bo, x, xa, Mrows, Dd, DMm, 1);

    // 5) LN2
    ln_kernel<<<Mrows, 256>>>(xa, ln2_w, ln2_b, x2);

    // 6) e = x2@we + be
    tgemm_kernel<<<dim3(DEe/128, Mrows/128), 256>>>(x2, we, be, nullptr, ep, Mrows, DEe, Dd, 0);

    // 7) sg = silu(x2@wg + bg)
    tgemm_kernel<<<dim3(DGg/128, Mrows/128), 256>>>(x2, wg, bg, nullptr, sg, Mrows, DGg, Dd, 2);

    // 8) e = silu(e * sigmoid(sg@wu + bu))   [fused eg epilogue, mode 4]
    tgemm_kernel<<<dim3(DEe/128, Mrows/128), 256>>>(sg, wu, bu, ep, ep, Mrows, DEe, DGg, 4);

    // 9) out = xa + e@wc + bc
    tgemm_kernel<<<dim3(Dd/128, Mrows/128), 256>>>(ep, wc, bc, xa, out, Mrows, Dd, DEe, 1);
}

// round 14
// speedup vs baseline: 1.1079x; 1.0801x over previous
#include <cuda_runtime.h>
#include <cuda_bf16.h>
#include <cstdint>

// ---------------------------------------------------------------------------
// Problem constants
// ---------------------------------------------------------------------------
#define Bq 2
#define Tt 2048
#define Dd 1024
#define DCc 512
#define DMm 1536
#define Hh 16
#define DEe 4096
#define DGg 1024
#define Mrows (Bq * Tt)          // 4096
#define CHD (DCc / Hh)           // 32
#define MHD (DMm / Hh)           // 96

// ---------------------------------------------------------------------------
// Scratch (device globals; cudaMalloc is forbidden)
// ---------------------------------------------------------------------------
__device__ float g_x1[Mrows * Dd];
__device__ float g_q [Mrows * DCc];
__device__ float g_k [Mrows * DCc];
__device__ float g_v [Mrows * DMm];
__device__ float g_y [Mrows * DMm];
__device__ float g_xa[Mrows * Dd];
__device__ float g_x2[Mrows * Dd];
__device__ float g_e [Mrows * DEe];
__device__ float g_sg[Mrows * DGg];

// ---------------------------------------------------------------------------
// helpers
// ---------------------------------------------------------------------------
__device__ __forceinline__ uint32_t f2tf32(float f) {
    uint32_t u;
    asm("cvt.rna.tf32.f32 %0, %1;" : "=r"(u) : "f"(f));
    return u;
}

__device__ __forceinline__ void mma_tf32(float* c, const uint32_t* a, const uint32_t* b) {
    asm volatile(
        "mma.sync.aligned.m16n8k8.row.col.f32.tf32.tf32.f32 "
        "{%0,%1,%2,%3}, {%4,%5,%6,%7}, {%8,%9}, {%0,%1,%2,%3};"
        : "+f"(c[0]), "+f"(c[1]), "+f"(c[2]), "+f"(c[3])
        : "r"(a[0]), "r"(a[1]), "r"(a[2]), "r"(a[3]), "r"(b[0]), "r"(b[1]));
}

__device__ __forceinline__ void cp_async16(void* smem, const void* gmem) {
    uint32_t s = (uint32_t)__cvta_generic_to_shared(smem);
    asm volatile("cp.async.cg.shared.global [%0], [%1], 16;" :: "r"(s), "l"(gmem));
}
__device__ __forceinline__ void cp_commit() {
    asm volatile("cp.async.commit_group;");
}
template <int N>
__device__ __forceinline__ void cp_wait() {
    asm volatile("cp.async.wait_group %0;" :: "n"(N));
}

// ---------------------------------------------------------------------------
// LayerNorm (unchanged)
// ---------------------------------------------------------------------------
__global__ __launch_bounds__(256) void ln_kernel(
    const float* __restrict__ x, const float* __restrict__ w,
    const float* __restrict__ b, float* __restrict__ out)
{
    int row = blockIdx.x;
    int tid = threadIdx.x;
    const float* xr = x + (size_t)row * Dd;
    float4 v = *(const float4*)(xr + tid * 4);
    float s  = v.x + v.y + v.z + v.w;
    float sq = v.x*v.x + v.y*v.y + v.z*v.z + v.w*v.w;
    #pragma unroll
    for (int o = 16; o > 0; o >>= 1) {
        s  += __shfl_xor_sync(0xffffffffu, s,  o);
        sq += __shfl_xor_sync(0xffffffffu, sq, o);
    }
    __shared__ float ss[8], ssq[8];
    int wid = tid >> 5, lid = tid & 31;
    if (lid == 0) { ss[wid] = s; ssq[wid] = sq; }
    __syncthreads();
    s = 0.f; sq = 0.f;
    #pragma unroll
    for (int i = 0; i < 8; i++) { s += ss[i]; sq += ssq[i]; }
    float mu  = s * (1.f / Dd);
    float var = sq * (1.f / Dd) - mu * mu;
    float rs  = rsqrtf(var + 1e-5f);
    float4 wv = *(const float4*)(w + tid * 4);
    float4 bv = *(const float4*)(b + tid * 4);
    float4 o;
    o.x = (v.x - mu) * rs * wv.x + bv.x;
    o.y = (v.y - mu) * rs * wv.y + bv.y;
    o.z = (v.z - mu) * rs * wv.z + bv.z;
    o.w = (v.w - mu) * rs * wv.w + bv.w;
    *(float4*)(out + (size_t)row * Dd + tid * 4) = o;
}

// ---------------------------------------------------------------------------
// TF32 tensor-core GEMM, cp.async 4-stage pipeline (deepened from round 7).
// modes: 0 bias, 1 +res, 2 SiLU, 3 sigmoid, 4 fused: C = silu(res*sigmoid(acc+bias))
// gridDim.z == 2 selects (W2, bias2, C2) for blockIdx.z == 1 (same code path).
// 128x128x16 tile, 256 threads, dynamic smem, 2 CTAs/SM.
// ---------------------------------------------------------------------------
#define AST 20
#define BST 136
#define NSTG 4
#define STAGE_F (128 * AST + 16 * BST)            // floats per stage: 4736
#define GEMM_SMEM (NSTG * STAGE_F * 4)            // 75776 bytes

__global__ __launch_bounds__(256) void tgemm_kernel(
    const float* __restrict__ A,
    const float* __restrict__ W,  const float* __restrict__ bias,
    const float* __restrict__ res, float* __restrict__ C,
    const float* __restrict__ W2, const float* __restrict__ bias2,
    float* __restrict__ C2,
    int M, int N, int K, int mode)
{
    extern __shared__ float smf[];
    // stage s: A at smf + s*STAGE_F (128x20), B at +128*AST (16x136)
    if (blockIdx.z) { W = W2; bias = bias2; C = C2; }

    int t = threadIdx.x;
    int bm = blockIdx.y * 128;
    int bn = blockIdx.x * 128;
    int lane = t & 31, wid = t >> 5;
    int r = lane >> 2, q = lane & 3;
    int m_base = (wid & 3) * 32;
    int n_base = (wid >> 2) * 64;

    int a_row0 = t >> 2;           // 0..63 (+64 for second chunk)
    int a_kc   = (t & 3) * 4;
    int b_row0 = t >> 5;           // 0..7 (+8 for second chunk)
    int b_col  = (t & 31) * 4;

    const int nk = K / 16;

    const float* Abase  = A + (size_t)(bm + a_row0) * K + a_kc;
    const float* Abase2 = Abase + (size_t)64 * K;
    const float* Wbase  = W + (size_t)b_row0 * N + bn + b_col;
    const float* Wbase2 = Wbase + (size_t)8 * N;

    float acc[2][8][4];
    #pragma unroll
    for (int i = 0; i < 2; i++)
        #pragma unroll
        for (int j = 0; j < 8; j++)
            #pragma unroll
            for (int c = 0; c < 4; c++) acc[i][j][c] = 0.f;

    #define STAGE_A(s) (smf + (s) * STAGE_F)
    #define STAGE_B(s) (smf + (s) * STAGE_F + 128 * AST)

    // prologue: issue stages 0,1,2
    #pragma unroll
    for (int s = 0; s < 3; s++) {
        int k0 = s * 16;
        cp_async16(STAGE_A(s) + a_row0 * AST + a_kc,        Abase  + k0);
        cp_async16(STAGE_A(s) + (a_row0 + 64) * AST + a_kc, Abase2 + k0);
        cp_async16(STAGE_B(s) + b_row0 * BST + b_col,       Wbase  + (size_t)k0 * N);
        cp_async16(STAGE_B(s) + (b_row0 + 8) * BST + b_col, Wbase2 + (size_t)k0 * N);
        cp_commit();
    }
    cp_wait<2>();
    __syncthreads();

    for (int kt = 0; kt < nk; kt++) {
        int buf = kt & 3;
        const float* As = STAGE_A(buf);
        const float* Bs = STAGE_B(buf);

        #pragma unroll
        for (int k8 = 0; k8 < 16; k8 += 8) {
            uint32_t a[2][4], b[8][2];
            #pragma unroll
            for (int mt = 0; mt < 2; mt++) {
                int m0 = m_base + mt * 16;
                a[mt][0] = __float_as_uint(As[(m0 + r    ) * AST + k8 + q]);
                a[mt][1] = __float_as_uint(As[(m0 + r + 8) * AST + k8 + q]);
                a[mt][2] = __float_as_uint(As[(m0 + r    ) * AST + k8 + q + 4]);
                a[mt][3] = __float_as_uint(As[(m0 + r + 8) * AST + k8 + q + 4]);
            }
            #pragma unroll
            for (int nt = 0; nt < 8; nt++) {
                int n0 = n_base + nt * 8;
                b[nt][0] = __float_as_uint(Bs[(k8 + q    ) * BST + n0 + r]);
                b[nt][1] = __float_as_uint(Bs[(k8 + q + 4) * BST + n0 + r]);
            }
            #pragma unroll
            for (int mt = 0; mt < 2; mt++)
                #pragma unroll
                for (int nt = 0; nt < 8; nt++)
                    mma_tf32(acc[mt][nt], a[mt], b[nt]);
        }

        // issue stage kt+3 into buf (kt+3)&3 (consumed at kt-1, safe after top barrier)
        if (kt + 3 < nk) {
            int s  = (kt + 3) & 3;
            int k0 = (kt + 3) * 16;
            cp_async16(STAGE_A(s) + a_row0 * AST + a_kc,        Abase  + k0);
            cp_async16(STAGE_A(s) + (a_row0 + 64) * AST + a_kc, Abase2 + k0);
            cp_async16(STAGE_B(s) + b_row0 * BST + b_col,       Wbase  + (size_t)k0 * N);
            cp_async16(STAGE_B(s) + (b_row0 + 8) * BST + b_col, Wbase2 + (size_t)k0 * N);
        }
        cp_commit();
        cp_wait<2>();
        __syncthreads();
    }

    // epilogue
    #pragma unroll
    for (int mt = 0; mt < 2; mt++) {
        int row0 = bm + m_base + mt * 16 + r;
        #pragma unroll
        for (int nt = 0; nt < 8; nt++) {
            int col = bn + n_base + nt * 8 + q * 2;
            float b0 = bias[col], b1 = bias[col + 1];
            float v0 = acc[mt][nt][0] + b0;
            float v1 = acc[mt][nt][1] + b1;
            float v2 = acc[mt][nt][2] + b0;
            float v3 = acc[mt][nt][3] + b1;
            if (mode == 1) {
                v0 += res[(size_t)row0 * N + col];
                v1 += res[(size_t)row0 * N + col + 1];
                v2 += res[(size_t)(row0 + 8) * N + col];
                v3 += res[(size_t)(row0 + 8) * N + col + 1];
            } else if (mode == 2) {
                v0 = v0 / (1.f + __expf(-v0));
                v1 = v1 / (1.f + __expf(-v1));
                v2 = v2 / (1.f + __expf(-v2));
                v3 = v3 / (1.f + __expf(-v3));
            } else if (mode == 3) {
                v0 = 1.f / (1.f + __expf(-v0));
                v1 = 1.f / (1.f + __expf(-v1));
                v2 = 1.f / (1.f + __expf(-v2));
                v3 = 1.f / (1.f + __expf(-v3));
            } else if (mode == 4) {
                float e0 = res[(size_t)row0 * N + col];
                float e1 = res[(size_t)row0 * N + col + 1];
                float e2 = res[(size_t)(row0 + 8) * N + col];
                float e3 = res[(size_t)(row0 + 8) * N + col + 1];
                float t0 = e0 * (1.f / (1.f + __expf(-v0)));
                float t1 = e1 * (1.f / (1.f + __expf(-v1)));
                float t2 = e2 * (1.f / (1.f + __expf(-v2)));
                float t3 = e3 * (1.f / (1.f + __expf(-v3)));
                v0 = t0 / (1.f + __expf(-t0));
                v1 = t1 / (1.f + __expf(-t1));
                v2 = t2 / (1.f + __expf(-t2));
                v3 = t3 / (1.f + __expf(-t3));
            }
            *(float2*)(C + (size_t)row0 * N + col)       = make_float2(v0, v1);
            *(float2*)(C + (size_t)(row0 + 8) * N + col) = make_float2(v2, v3);
        }
    }
}

// ---------------------------------------------------------------------------
// TF32 MMA flash attention (round-7 version, unchanged)
// ---------------------------------------------------------------------------
#define AT_KST 36
#define AT_VST 68
#define AT_SST 68
#define ATTN_SMEM ((64*AT_KST + 96*AT_VST + 4*16*AT_SST) * 4)

__global__ __launch_bounds__(128) void attn_mma_kernel(
    const float* __restrict__ q, const float* __restrict__ k,
    const float* __restrict__ v, float* __restrict__ y)
{
    extern __shared__ float sm[];
    float* Ks = sm;
    float* Vs = Ks + 64 * AT_KST;
    float* Ss = Vs + 96 * AT_VST;

    int tid  = threadIdx.x;
    int wid  = tid >> 5, lane = tid & 31;
    int r    = lane >> 2, qd = lane & 3;
    int qt   = blockIdx.x;
    int bh   = blockIdx.y;
    int b    = bh >> 4, h = bh & 15;
    int q0   = qt * 64;
    int mrow = wid * 16;

    const float* qbase = q + (size_t)b * Tt * DCc + h * CHD;
    const float* kbase = k + (size_t)b * Tt * DCc + h * CHD;
    const float* vbase = v + (size_t)b * Tt * DMm + h * MHD;

    const float scale = 0.17677669529663687f;
    int grow0 = q0 + mrow + r;
    uint32_t qa[4][4];
    #pragma unroll
    for (int ks = 0; ks < 4; ks++) {
        qa[ks][0] = f2tf32(qbase[(size_t)grow0       * DCc + ks * 8 + qd    ] * scale);
        qa[ks][1] = f2tf32(qbase[(size_t)(grow0 + 8) * DCc + ks * 8 + qd    ] * scale);
        qa[ks][2] = f2tf32(qbase[(size_t)grow0       * DCc + ks * 8 + qd + 4] * scale);
        qa[ks][3] = f2tf32(qbase[(size_t)(grow0 + 8) * DCc + ks * 8 + qd + 4] * scale);
    }

    float m0 = -1e30f, m1 = -1e30f, l0 = 0.f, l1 = 0.f;
    float o[12][4];
    #pragma unroll
    for (int nt = 0; nt < 12; nt++)
        #pragma unroll
        for (int c = 0; c < 4; c++) o[nt][c] = 0.f;

    float* Sw = Ss + wid * 16 * AT_SST;

    for (int j = 0; j <= qt; j++) {
        int k0 = j * 64;
        __syncthreads();
        {
            int row = tid >> 1;
            int c0  = (tid & 1) * 16;
            const float* src = kbase + (size_t)(k0 + row) * DCc + c0;
            uint32_t* dst = (uint32_t*)&Ks[row * AT_KST + c0];
            #pragma unroll
            for (int jj = 0; jj < 4; jj++) {
                float4 f = *(const float4*)(src + jj * 4);
                uint4 u = make_uint4(f2tf32(f.x), f2tf32(f.y), f2tf32(f.z), f2tf32(f.w));
                *(uint4*)(dst + jj * 4) = u;
            }
        }
        {
            #pragma unroll
            for (int it = 0; it < 12; it++) {
                int idx  = it * 128 + tid;
                int trow = idx / 24, c4 = idx % 24;
                float4 f = *(const float4*)(vbase + (size_t)(k0 + trow) * DMm + c4 * 4);
                Vs[(c4 * 4 + 0) * AT_VST + trow] = __uint_as_float(f2tf32(f.x));
                Vs[(c4 * 4 + 1) * AT_VST + trow] = __uint_as_float(f2tf32(f.y));
                Vs[(c4 * 4 + 2) * AT_VST + trow] = __uint_as_float(f2tf32(f.z));
                Vs[(c4 * 4 + 3) * AT_VST + trow] = __uint_as_float(f2tf32(f.w));
            }
        }
        __syncthreads();

        float sc[8][4];
        #pragma unroll
        for (int nt = 0; nt < 8; nt++)
            #pragma unroll
            for (int c = 0; c < 4; c++) sc[nt][c] = 0.f;
        #pragma unroll
        for (int ks = 0; ks < 4; ks++) {
            #pragma unroll
            for (int nt = 0; nt < 8; nt++) {
                uint32_t bb[2];
                bb[0] = __float_as_uint(Ks[(nt * 8 + r) * AT_KST + ks * 8 + qd    ]);
                bb[1] = __float_as_uint(Ks[(nt * 8 + r) * AT_KST + ks * 8 + qd + 4]);
                mma_tf32(sc[nt], qa[ks], bb);
            }
        }

        float mx0 = -1e30f, mx1 = -1e30f;
        #pragma unroll
        for (int nt = 0; nt < 8; nt++) {
            int c = k0 + nt * 8 + 2 * qd;
            if (c     > grow0    ) sc[nt][0] = -1e30f;
            if (c + 1 > grow0    ) sc[nt][1] = -1e30f;
            if (c     > grow0 + 8) sc[nt][2] = -1e30f;
            if (c + 1 > grow0 + 8) sc[nt][3] = -1e30f;
            mx0 = fmaxf(mx0, fmaxf(sc[nt][0], sc[nt][1]));
            mx1 = fmaxf(mx1, fmaxf(sc[nt][2], sc[nt][3]));
        }
        mx0 = fmaxf(mx0, __shfl_xor_sync(0xffffffffu, mx0, 1));
        mx0 = fmaxf(mx0, __shfl_xor_sync(0xffffffffu, mx0, 2));
        mx1 = fmaxf(mx1, __shfl_xor_sync(0xffffffffu, mx1, 1));
        mx1 = fmaxf(mx1, __shfl_xor_sync(0xffffffffu, mx1, 2));

        float mn0 = fmaxf(m0, mx0), mn1 = fmaxf(m1, mx1);
        float corr0 = __expf(m0 - mn0), corr1 = __expf(m1 - mn1);
        float s0 = 0.f, s1 = 0.f;
        #pragma unroll
        for (int nt = 0; nt < 8; nt++) {
            float p00 = __expf(sc[nt][0] - mn0);
            float p01 = __expf(sc[nt][1] - mn0);
            float p10 = __expf(sc[nt][2] - mn1);
            float p11 = __expf(sc[nt][3] - mn1);
            s0 += p00 + p01;
            s1 += p10 + p11;
            int cb = nt * 8 + 2 * qd;
            Sw[r * AT_SST + cb]           = __uint_as_float(f2tf32(p00));
            Sw[r * AT_SST + cb + 1]       = __uint_as_float(f2tf32(p01));
            Sw[(r + 8) * AT_SST + cb]     = __uint_as_float(f2tf32(p10));
            Sw[(r + 8) * AT_SST + cb + 1] = __uint_as_float(f2tf32(p11));
        }
        s0 += __shfl_xor_sync(0xffffffffu, s0, 1);
        s0 += __shfl_xor_sync(0xffffffffu, s0, 2);
        s1 += __shfl_xor_sync(0xffffffffu, s1, 1);
        s1 += __shfl_xor_sync(0xffffffffu, s1, 2);
        l0 = l0 * corr0 + s0;
        l1 = l1 * corr1 + s1;
        m0 = mn0; m1 = mn1;
        #pragma unroll
        for (int nt = 0; nt < 12; nt++) {
            o[nt][0] *= corr0; o[nt][1] *= corr0;
            o[nt][2] *= corr1; o[nt][3] *= corr1;
        }
        __syncwarp();

        #pragma unroll
        for (int ks = 0; ks < 8; ks++) {
            uint32_t pa[4];
            pa[0] = __float_as_uint(Sw[r       * AT_SST + ks * 8 + qd    ]);
            pa[1] = __float_as_uint(Sw[(r + 8) * AT_SST + ks * 8 + qd    ]);
            pa[2] = __float_as_uint(Sw[r       * AT_SST + ks * 8 + qd + 4]);
            pa[3] = __float_as_uint(Sw[(r + 8) * AT_SST + ks * 8 + qd + 4]);
            #pragma unroll
            for (int nt = 0; nt < 12; nt++) {
                uint32_t bb[2];
                bb[0] = __float_as_uint(Vs[(nt * 8 + r) * AT_VST + ks * 8 + qd    ]);
                bb[1] = __float_as_uint(Vs[(nt * 8 + r) * AT_VST + ks * 8 + qd + 4]);
                mma_tf32(o[nt], pa, bb);
            }
        }
        __syncwarp();
    }

    float inv0 = 1.f / l0, inv1 = 1.f / l1;
    float* yb = y + (size_t)b * Tt * DMm + h * MHD;
    #pragma unroll
    for (int nt = 0; nt < 12; nt++) {
        int cb = nt * 8 + 2 * qd;
        *(float2*)(yb + (size_t)grow0 * DMm + cb) =
            make_float2(o[nt][0] * inv0, o[nt][1] * inv0);
        *(float2*)(yb + (size_t)(grow0 + 8) * DMm + cb) =
            make_float2(o[nt][2] * inv1, o[nt][3] * inv1);
    }
}

// ---------------------------------------------------------------------------
// Host launcher
// ---------------------------------------------------------------------------
extern "C" void kernel_launch(void* const* d_in, const int* in_sizes, int n_in,
                              void* d_out, int out_size)
{
    const float* x     = (const float*)d_in[0];
    const float* ln1_w = (const float*)d_in[2];
    const float* ln1_b = (const float*)d_in[3];
    const float* wq    = (const float*)d_in[4];
    const float* bq    = (const float*)d_in[5];
    const float* wk    = (const float*)d_in[6];
    const float* bk    = (const float*)d_in[7];
    const float* wv    = (const float*)d_in[8];
    const float* bv    = (const float*)d_in[9];
    const float* wo    = (const float*)d_in[10];
    const float* bo    = (const float*)d_in[11];
    const float* ln2_w = (const float*)d_in[12];
    const float* ln2_b = (const float*)d_in[13];
    const float* we    = (const float*)d_in[14];
    const float* be    = (const float*)d_in[15];
    const float* wg    = (const float*)d_in[16];
    const float* bg    = (const float*)d_in[17];
    const float* wu    = (const float*)d_in[18];
    const float* bu    = (const float*)d_in[19];
    const float* wc    = (const float*)d_in[20];
    const float* bc    = (const float*)d_in[21];
    float* out = (float*)d_out;

    float *x1, *qp, *kp, *vp, *yp, *xa, *x2, *ep, *sg;
    cudaGetSymbolAddress((void**)&x1, g_x1);
    cudaGetSymbolAddress((void**)&qp, g_q);
    cudaGetSymbolAddress((void**)&kp, g_k);
    cudaGetSymbolAddress((void**)&vp, g_v);
    cudaGetSymbolAddress((void**)&yp, g_y);
    cudaGetSymbolAddress((void**)&xa, g_xa);
    cudaGetSymbolAddress((void**)&x2, g_x2);
    cudaGetSymbolAddress((void**)&ep, g_e);
    cudaGetSymbolAddress((void**)&sg, g_sg);

    cudaFuncSetAttribute(attn_mma_kernel,
                         cudaFuncAttributeMaxDynamicSharedMemorySize, ATTN_SMEM);
    cudaFuncSetAttribute(tgemm_kernel,
                         cudaFuncAttributeMaxDynamicSharedMemorySize, GEMM_SMEM);

    // 1) LN1
    ln_kernel<<<Mrows, 256>>>(x, ln1_w, ln1_b, x1);

    // 2) Q and K in ONE launch (grid.z selects weights; single code path), then V
    tgemm_kernel<<<dim3(DCc/128, Mrows/128, 2), 256, GEMM_SMEM>>>(
        x1, wq, bq, nullptr, qp, wk, bk, kp, Mrows, DCc, Dd, 0);
    tgemm_kernel<<<dim3(DMm/128, Mrows/128, 1), 256, GEMM_SMEM>>>(
        x1, wv, bv, nullptr, vp, nullptr, nullptr, nullptr, Mrows, DMm, Dd, 0);

    // 3) causal attention (TF32 MMA)
    attn_mma_kernel<<<dim3(Tt/64, Bq*Hh), 128, ATTN_SMEM>>>(qp, kp, vp, yp);

    // 4) output projection + residual
    tgemm_kernel<<<dim3(Dd/128, Mrows/128, 1), 256, GEMM_SMEM>>>(
        yp, wo, bo, x, xa, nullptr, nullptr, nullptr, Mrows, Dd, DMm, 1);

    // 5) LN2
    ln_kernel<<<Mrows, 256>>>(xa, ln2_w, ln2_b, x2);

    // 6) e = x2@we + be
    tgemm_kernel<<<dim3(DEe/128, Mrows/128, 1), 256, GEMM_SMEM>>>(
        x2, we, be, nullptr, ep, nullptr, nullptr, nullptr, Mrows, DEe, Dd, 0);

    // 7) sg = silu(x2@wg + bg)
    tgemm_kernel<<<dim3(DGg/128, Mrows/128, 1), 256, GEMM_SMEM>>>(
        x2, wg, bg, nullptr, sg, nullptr, nullptr, nullptr, Mrows, DGg, Dd, 2);

    // 8) e = silu(e * sigmoid(sg@wu + bu))   [fused eg epilogue, mode 4]
    tgemm_kernel<<<dim3(DEe/128, Mrows/128, 1), 256, GEMM_SMEM>>>(
        sg, wu, bu, ep, ep, nullptr, nullptr, nullptr, Mrows, DEe, DGg, 4);

    // 9) out = xa + e@wc + bc
    tgemm_kernel<<<dim3(Dd/128, Mrows/128, 1), 256, GEMM_SMEM>>>(
        ep, wc, bc, xa, out, nullptr, nullptr, nullptr, Mrows, Dd, DEe, 1);
}

// round 16
// speedup vs baseline: 1.1975x; 1.0809x over previous
#include <cuda_runtime.h>
#include <cuda_bf16.h>
#include <cstdint>

// ---------------------------------------------------------------------------
// Problem constants
// ---------------------------------------------------------------------------
#define Bq 2
#define Tt 2048
#define Dd 1024
#define DCc 512
#define DMm 1536
#define Hh 16
#define DEe 4096
#define DGg 1024
#define Mrows (Bq * Tt)          // 4096
#define CHD (DCc / Hh)           // 32
#define MHD (DMm / Hh)           // 96

// ---------------------------------------------------------------------------
// Scratch (device globals; cudaMalloc is forbidden)
// ---------------------------------------------------------------------------
__device__ float g_x1[Mrows * Dd];
__device__ float g_q [Mrows * DCc];
__device__ float g_k [Mrows * DCc];
__device__ float g_v [Mrows * DMm];
__device__ float g_y [Mrows * DMm];
__device__ float g_xa[Mrows * Dd];
__device__ float g_x2[Mrows * Dd];
__device__ float g_e [Mrows * DEe];
__device__ float g_sg[Mrows * DGg];

// ---------------------------------------------------------------------------
// helpers
// ---------------------------------------------------------------------------
__device__ __forceinline__ void mma_tf32(float* c, const uint32_t* a, const uint32_t* b) {
    asm volatile(
        "mma.sync.aligned.m16n8k8.row.col.f32.tf32.tf32.f32 "
        "{%0,%1,%2,%3}, {%4,%5,%6,%7}, {%8,%9}, {%0,%1,%2,%3};"
        : "+f"(c[0]), "+f"(c[1]), "+f"(c[2]), "+f"(c[3])
        : "r"(a[0]), "r"(a[1]), "r"(a[2]), "r"(a[3]), "r"(b[0]), "r"(b[1]));
}

__device__ __forceinline__ void cp_async16(void* smem, const void* gmem) {
    uint32_t s = (uint32_t)__cvta_generic_to_shared(smem);
    asm volatile("cp.async.cg.shared.global [%0], [%1], 16;" :: "r"(s), "l"(gmem));
}
__device__ __forceinline__ void cp_commit() {
    asm volatile("cp.async.commit_group;");
}
template <int N>
__device__ __forceinline__ void cp_wait() {
    asm volatile("cp.async.wait_group %0;" :: "n"(N));
}

// ---------------------------------------------------------------------------
// LayerNorm (unchanged)
// ---------------------------------------------------------------------------
__global__ __launch_bounds__(256) void ln_kernel(
    const float* __restrict__ x, const float* __restrict__ w,
    const float* __restrict__ b, float* __restrict__ out)
{
    int row = blockIdx.x;
    int tid = threadIdx.x;
    const float* xr = x + (size_t)row * Dd;
    float4 v = *(const float4*)(xr + tid * 4);
    float s  = v.x + v.y + v.z + v.w;
    float sq = v.x*v.x + v.y*v.y + v.z*v.z + v.w*v.w;
    #pragma unroll
    for (int o = 16; o > 0; o >>= 1) {
        s  += __shfl_xor_sync(0xffffffffu, s,  o);
        sq += __shfl_xor_sync(0xffffffffu, sq, o);
    }
    __shared__ float ss[8], ssq[8];
    int wid = tid >> 5, lid = tid & 31;
    if (lid == 0) { ss[wid] = s; ssq[wid] = sq; }
    __syncthreads();
    s = 0.f; sq = 0.f;
    #pragma unroll
    for (int i = 0; i < 8; i++) { s += ss[i]; sq += ssq[i]; }
    float mu  = s * (1.f / Dd);
    float var = sq * (1.f / Dd) - mu * mu;
    float rs  = rsqrtf(var + 1e-5f);
    float4 wv = *(const float4*)(w + tid * 4);
    float4 bv = *(const float4*)(b + tid * 4);
    float4 o;
    o.x = (v.x - mu) * rs * wv.x + bv.x;
    o.y = (v.y - mu) * rs * wv.y + bv.y;
    o.z = (v.z - mu) * rs * wv.z + bv.z;
    o.w = (v.w - mu) * rs * wv.w + bv.w;
    *(float4*)(out + (size_t)row * Dd + tid * 4) = o;
}

// ---------------------------------------------------------------------------
// TF32 tensor-core GEMM, cp.async 4-stage pipeline (round-14, passed).
// modes: 0 bias, 1 +res, 2 SiLU, 3 sigmoid, 4 fused: C = silu(res*sigmoid(acc+bias))
// gridDim.z == 2 selects (W2, bias2, C2) for blockIdx.z == 1 (same code path).
// ---------------------------------------------------------------------------
#define AST 20
#define BST 136
#define NSTG 4
#define STAGE_F (128 * AST + 16 * BST)            // floats per stage: 4736
#define GEMM_SMEM (NSTG * STAGE_F * 4)            // 75776 bytes

__global__ __launch_bounds__(256) void tgemm_kernel(
    const float* __restrict__ A,
    const float* __restrict__ W,  const float* __restrict__ bias,
    const float* __restrict__ res, float* __restrict__ C,
    const float* __restrict__ W2, const float* __restrict__ bias2,
    float* __restrict__ C2,
    int M, int N, int K, int mode)
{
    extern __shared__ float smf[];
    if (blockIdx.z) { W = W2; bias = bias2; C = C2; }

    int t = threadIdx.x;
    int bm = blockIdx.y * 128;
    int bn = blockIdx.x * 128;
    int lane = t & 31, wid = t >> 5;
    int r = lane >> 2, q = lane & 3;
    int m_base = (wid & 3) * 32;
    int n_base = (wid >> 2) * 64;

    int a_row0 = t >> 2;
    int a_kc   = (t & 3) * 4;
    int b_row0 = t >> 5;
    int b_col  = (t & 31) * 4;

    const int nk = K / 16;

    const float* Abase  = A + (size_t)(bm + a_row0) * K + a_kc;
    const float* Abase2 = Abase + (size_t)64 * K;
    const float* Wbase  = W + (size_t)b_row0 * N + bn + b_col;
    const float* Wbase2 = Wbase + (size_t)8 * N;

    float acc[2][8][4];
    #pragma unroll
    for (int i = 0; i < 2; i++)
        #pragma unroll
        for (int j = 0; j < 8; j++)
            #pragma unroll
            for (int c = 0; c < 4; c++) acc[i][j][c] = 0.f;

    #define STAGE_A(s) (smf + (s) * STAGE_F)
    #define STAGE_B(s) (smf + (s) * STAGE_F + 128 * AST)

    #pragma unroll
    for (int s = 0; s < 3; s++) {
        int k0 = s * 16;
        cp_async16(STAGE_A(s) + a_row0 * AST + a_kc,        Abase  + k0);
        cp_async16(STAGE_A(s) + (a_row0 + 64) * AST + a_kc, Abase2 + k0);
        cp_async16(STAGE_B(s) + b_row0 * BST + b_col,       Wbase  + (size_t)k0 * N);
        cp_async16(STAGE_B(s) + (b_row0 + 8) * BST + b_col, Wbase2 + (size_t)k0 * N);
        cp_commit();
    }
    cp_wait<2>();
    __syncthreads();

    for (int kt = 0; kt < nk; kt++) {
        int buf = kt & 3;
        const float* As = STAGE_A(buf);
        const float* Bs = STAGE_B(buf);

        #pragma unroll
        for (int k8 = 0; k8 < 16; k8 += 8) {
            uint32_t a[2][4], b[8][2];
            #pragma unroll
            for (int mt = 0; mt < 2; mt++) {
                int m0 = m_base + mt * 16;
                a[mt][0] = __float_as_uint(As[(m0 + r    ) * AST + k8 + q]);
                a[mt][1] = __float_as_uint(As[(m0 + r + 8) * AST + k8 + q]);
                a[mt][2] = __float_as_uint(As[(m0 + r    ) * AST + k8 + q + 4]);
                a[mt][3] = __float_as_uint(As[(m0 + r + 8) * AST + k8 + q + 4]);
            }
            #pragma unroll
            for (int nt = 0; nt < 8; nt++) {
                int n0 = n_base + nt * 8;
                b[nt][0] = __float_as_uint(Bs[(k8 + q    ) * BST + n0 + r]);
                b[nt][1] = __float_as_uint(Bs[(k8 + q + 4) * BST + n0 + r]);
            }
            #pragma unroll
            for (int mt = 0; mt < 2; mt++)
                #pragma unroll
                for (int nt = 0; nt < 8; nt++)
                    mma_tf32(acc[mt][nt], a[mt], b[nt]);
        }

        if (kt + 3 < nk) {
            int s  = (kt + 3) & 3;
            int k0 = (kt + 3) * 16;
            cp_async16(STAGE_A(s) + a_row0 * AST + a_kc,        Abase  + k0);
            cp_async16(STAGE_A(s) + (a_row0 + 64) * AST + a_kc, Abase2 + k0);
            cp_async16(STAGE_B(s) + b_row0 * BST + b_col,       Wbase  + (size_t)k0 * N);
            cp_async16(STAGE_B(s) + (b_row0 + 8) * BST + b_col, Wbase2 + (size_t)k0 * N);
        }
        cp_commit();
        cp_wait<2>();
        __syncthreads();
    }

    #pragma unroll
    for (int mt = 0; mt < 2; mt++) {
        int row0 = bm + m_base + mt * 16 + r;
        #pragma unroll
        for (int nt = 0; nt < 8; nt++) {
            int col = bn + n_base + nt * 8 + q * 2;
            float b0 = bias[col], b1 = bias[col + 1];
            float v0 = acc[mt][nt][0] + b0;
            float v1 = acc[mt][nt][1] + b1;
            float v2 = acc[mt][nt][2] + b0;
            float v3 = acc[mt][nt][3] + b1;
            if (mode == 1) {
                v0 += res[(size_t)row0 * N + col];
                v1 += res[(size_t)row0 * N + col + 1];
                v2 += res[(size_t)(row0 + 8) * N + col];
                v3 += res[(size_t)(row0 + 8) * N + col + 1];
            } else if (mode == 2) {
                v0 = v0 / (1.f + __expf(-v0));
                v1 = v1 / (1.f + __expf(-v1));
                v2 = v2 / (1.f + __expf(-v2));
                v3 = v3 / (1.f + __expf(-v3));
            } else if (mode == 3) {
                v0 = 1.f / (1.f + __expf(-v0));
                v1 = 1.f / (1.f + __expf(-v1));
                v2 = 1.f / (1.f + __expf(-v2));
                v3 = 1.f / (1.f + __expf(-v3));
            } else if (mode == 4) {
                float e0 = res[(size_t)row0 * N + col];
                float e1 = res[(size_t)row0 * N + col + 1];
                float e2 = res[(size_t)(row0 + 8) * N + col];
                float e3 = res[(size_t)(row0 + 8) * N + col + 1];
                float t0 = e0 * (1.f / (1.f + __expf(-v0)));
                float t1 = e1 * (1.f / (1.f + __expf(-v1)));
                float t2 = e2 * (1.f / (1.f + __expf(-v2)));
                float t3 = e3 * (1.f / (1.f + __expf(-v3)));
                v0 = t0 / (1.f + __expf(-t0));
                v1 = t1 / (1.f + __expf(-t1));
                v2 = t2 / (1.f + __expf(-t2));
                v3 = t3 / (1.f + __expf(-t3));
            }
            *(float2*)(C + (size_t)row0 * N + col)       = make_float2(v0, v1);
            *(float2*)(C + (size_t)(row0 + 8) * N + col) = make_float2(v2, v3);
        }
    }
}

// ---------------------------------------------------------------------------
// TF32 MMA flash attention, cp.async double-buffered K/V, V row-major.
// 64 q-rows x 1 head per block, 4 warps. Heaviest q-tiles scheduled first.
// ---------------------------------------------------------------------------
#define AT_KST 36      // K tile stride (floats); banks (4r+qd) all distinct
#define AT_VST 104     // V tile stride (floats); banks (8qd+r) all distinct
#define AT_SST 68
#define AT_KTILE (64 * AT_KST)     // 2304 floats
#define AT_VTILE (64 * AT_VST)     // 6656 floats
#define ATTN_SMEM ((2*AT_KTILE + 2*AT_VTILE + 4*16*AT_SST) * 4)   // 89088 B

__global__ __launch_bounds__(128) void attn_mma_kernel(
    const float* __restrict__ q, const float* __restrict__ k,
    const float* __restrict__ v, float* __restrict__ y)
{
    extern __shared__ float sm[];
    float* Kb = sm;                        // [2][64][AT_KST]
    float* Vb = sm + 2 * AT_KTILE;         // [2][64][AT_VST]
    float* Ss = Vb + 2 * AT_VTILE;         // [4][16][AT_SST]

    int tid  = threadIdx.x;
    int wid  = tid >> 5, lane = tid & 31;
    int r    = lane >> 2, qd = lane & 3;
    int qt   = (gridDim.x - 1) - blockIdx.x;   // heavy tiles first
    int bh   = blockIdx.y;
    int b    = bh >> 4, h = bh & 15;
    int q0   = qt * 64;
    int mrow = wid * 16;

    const float* qbase = q + (size_t)b * Tt * DCc + h * CHD;
    const float* kbase = k + (size_t)b * Tt * DCc + h * CHD;
    const float* vbase = v + (size_t)b * Tt * DMm + h * MHD;

    const float scale = 0.17677669529663687f;
    int grow0 = q0 + mrow + r;
    uint32_t qa[4][4];
    #pragma unroll
    for (int ks = 0; ks < 4; ks++) {
        qa[ks][0] = __float_as_uint(qbase[(size_t)grow0       * DCc + ks * 8 + qd    ] * scale);
        qa[ks][1] = __float_as_uint(qbase[(size_t)(grow0 + 8) * DCc + ks * 8 + qd    ] * scale);
        qa[ks][2] = __float_as_uint(qbase[(size_t)grow0       * DCc + ks * 8 + qd + 4] * scale);
        qa[ks][3] = __float_as_uint(qbase[(size_t)(grow0 + 8) * DCc + ks * 8 + qd + 4] * scale);
    }

    float m0 = -1e30f, m1 = -1e30f, l0 = 0.f, l1 = 0.f;
    float o[12][4];
    #pragma unroll
    for (int nt = 0; nt < 12; nt++)
        #pragma unroll
        for (int c = 0; c < 4; c++) o[nt][c] = 0.f;

    float* Sw = Ss + wid * 16 * AT_SST;

    // tile loader: pure cp.async (K: 4 chunks/thread; V: 12 chunks/thread)
    #define AT_LOAD(bufi, kk)                                                  \
        do {                                                                   \
            float* Kd = Kb + (bufi) * AT_KTILE;                                \
            float* Vd = Vb + (bufi) * AT_VTILE;                                \
            _Pragma("unroll")                                                  \
            for (int i = 0; i < 4; i++) {                                      \
                int c = tid + i * 128;                                         \
                int row = c >> 3, c8 = c & 7;                                  \
                cp_async16(Kd + row * AT_KST + c8 * 4,                         \
                           kbase + (size_t)((kk) + row) * DCc + c8 * 4);       \
            }                                                                  \
            _Pragma("unroll")                                                  \
            for (int i = 0; i < 12; i++) {                                     \
                int c = tid + i * 128;                                         \
                int row = c / 24, c24 = c % 24;                                \
                cp_async16(Vd + row * AT_VST + c24 * 4,                        \
                           vbase + (size_t)((kk) + row) * DMm + c24 * 4);      \
            }                                                                  \
        } while (0)

    // prologue: tile 0 -> buf 0
    AT_LOAD(0, 0);
    cp_commit();

    for (int j = 0; j <= qt; j++) {
        int buf = j & 1;
        if (j < qt) AT_LOAD(buf ^ 1, (j + 1) * 64);
        cp_commit();
        cp_wait<1>();
        __syncthreads();

        const float* Ks = Kb + buf * AT_KTILE;
        const float* Vs = Vb + buf * AT_VTILE;
        int k0 = j * 64;

        // S = Q @ K^T  (16 x 64 per warp)
        float sc[8][4];
        #pragma unroll
        for (int nt = 0; nt < 8; nt++)
            #pragma unroll
            for (int c = 0; c < 4; c++) sc[nt][c] = 0.f;
        #pragma unroll
        for (int ks = 0; ks < 4; ks++) {
            #pragma unroll
            for (int nt = 0; nt < 8; nt++) {
                uint32_t bb[2];
                bb[0] = __float_as_uint(Ks[(nt * 8 + r) * AT_KST + ks * 8 + qd    ]);
                bb[1] = __float_as_uint(Ks[(nt * 8 + r) * AT_KST + ks * 8 + qd + 4]);
                mma_tf32(sc[nt], qa[ks], bb);
            }
        }

        // causal mask + online softmax
        float mx0 = -1e30f, mx1 = -1e30f;
        #pragma unroll
        for (int nt = 0; nt < 8; nt++) {
            int c = k0 + nt * 8 + 2 * qd;
            if (c     > grow0    ) sc[nt][0] = -1e30f;
            if (c + 1 > grow0    ) sc[nt][1] = -1e30f;
            if (c     > grow0 + 8) sc[nt][2] = -1e30f;
            if (c + 1 > grow0 + 8) sc[nt][3] = -1e30f;
            mx0 = fmaxf(mx0, fmaxf(sc[nt][0], sc[nt][1]));
            mx1 = fmaxf(mx1, fmaxf(sc[nt][2], sc[nt][3]));
        }
        mx0 = fmaxf(mx0, __shfl_xor_sync(0xffffffffu, mx0, 1));
        mx0 = fmaxf(mx0, __shfl_xor_sync(0xffffffffu, mx0, 2));
        mx1 = fmaxf(mx1, __shfl_xor_sync(0xffffffffu, mx1, 1));
        mx1 = fmaxf(mx1, __shfl_xor_sync(0xffffffffu, mx1, 2));

        float mn0 = fmaxf(m0, mx0), mn1 = fmaxf(m1, mx1);
        float corr0 = __expf(m0 - mn0), corr1 = __expf(m1 - mn1);
        float s0 = 0.f, s1 = 0.f;
        #pragma unroll
        for (int nt = 0; nt < 8; nt++) {
            float p00 = __expf(sc[nt][0] - mn0);
            float p01 = __expf(sc[nt][1] - mn0);
            float p10 = __expf(sc[nt][2] - mn1);
            float p11 = __expf(sc[nt][3] - mn1);
            s0 += p00 + p01;
            s1 += p10 + p11;
            int cb = nt * 8 + 2 * qd;
            Sw[r * AT_SST + cb]           = p00;
            Sw[r * AT_SST + cb + 1]       = p01;
            Sw[(r + 8) * AT_SST + cb]     = p10;
            Sw[(r + 8) * AT_SST + cb + 1] = p11;
        }
        s0 += __shfl_xor_sync(0xffffffffu, s0, 1);
        s0 += __shfl_xor_sync(0xffffffffu, s0, 2);
        s1 += __shfl_xor_sync(0xffffffffu, s1, 1);
        s1 += __shfl_xor_sync(0xffffffffu, s1, 2);
        l0 = l0 * corr0 + s0;
        l1 = l1 * corr1 + s1;
        m0 = mn0; m1 = mn1;
        #pragma unroll
        for (int nt = 0; nt < 12; nt++) {
            o[nt][0] *= corr0; o[nt][1] *= corr0;
            o[nt][2] *= corr1; o[nt][3] *= corr1;
        }
        __syncwarp();

        // O += P @ V  (V row-major: B fragment from Vs[kv][dim])
        #pragma unroll
        for (int ks = 0; ks < 8; ks++) {
            uint32_t pa[4];
            pa[0] = __float_as_uint(Sw[r       * AT_SST + ks * 8 + qd    ]);
            pa[1] = __float_as_uint(Sw[(r + 8) * AT_SST + ks * 8 + qd    ]);
            pa[2] = __float_as_uint(Sw[r       * AT_SST + ks * 8 + qd + 4]);
            pa[3] = __float_as_uint(Sw[(r + 8) * AT_SST + ks * 8 + qd + 4]);
            #pragma unroll
            for (int nt = 0; nt < 12; nt++) {
                uint32_t bb[2];
                bb[0] = __float_as_uint(Vs[(ks * 8 + qd    ) * AT_VST + nt * 8 + r]);
                bb[1] = __float_as_uint(Vs[(ks * 8 + qd + 4) * AT_VST + nt * 8 + r]);
                mma_tf32(o[nt], pa, bb);
            }
        }
        __syncthreads();   // all warps done with buf before prefetch overwrites it
    }

    float inv0 = 1.f / l0, inv1 = 1.f / l1;
    float* yb = y + (size_t)b * Tt * DMm + h * MHD;
    #pragma unroll
    for (int nt = 0; nt < 12; nt++) {
        int cb = nt * 8 + 2 * qd;
        *(float2*)(yb + (size_t)grow0 * DMm + cb) =
            make_float2(o[nt][0] * inv0, o[nt][1] * inv0);
        *(float2*)(yb + (size_t)(grow0 + 8) * DMm + cb) =
            make_float2(o[nt][2] * inv1, o[nt][3] * inv1);
    }
}

// ---------------------------------------------------------------------------
// Host launcher
// ---------------------------------------------------------------------------
extern "C" void kernel_launch(void* const* d_in, const int* in_sizes, int n_in,
                              void* d_out, int out_size)
{
    const float* x     = (const float*)d_in[0];
    const float* ln1_w = (const float*)d_in[2];
    const float* ln1_b = (const float*)d_in[3];
    const float* wq    = (const float*)d_in[4];
    const float* bq    = (const float*)d_in[5];
    const float* wk    = (const float*)d_in[6];
    const float* bk    = (const float*)d_in[7];
    const float* wv    = (const float*)d_in[8];
    const float* bv    = (const float*)d_in[9];
    const float* wo    = (const float*)d_in[10];
    const float* bo    = (const float*)d_in[11];
    const float* ln2_w = (const float*)d_in[12];
    const float* ln2_b = (const float*)d_in[13];
    const float* we    = (const float*)d_in[14];
    const float* be    = (const float*)d_in[15];
    const float* wg    = (const float*)d_in[16];
    const float* bg    = (const float*)d_in[17];
    const float* wu    = (const float*)d_in[18];
    const float* bu    = (const float*)d_in[19];
    const float* wc    = (const float*)d_in[20];
    const float* bc    = (const float*)d_in[21];
    float* out = (float*)d_out;

    float *x1, *qp, *kp, *vp, *yp, *xa, *x2, *ep, *sg;
    cudaGetSymbolAddress((void**)&x1, g_x1);
    cudaGetSymbolAddress((void**)&qp, g_q);
    cudaGetSymbolAddress((void**)&kp, g_k);
    cudaGetSymbolAddress((void**)&vp, g_v);
    cudaGetSymbolAddress((void**)&yp, g_y);
    cudaGetSymbolAddress((void**)&xa, g_xa);
    cudaGetSymbolAddress((void**)&x2, g_x2);
    cudaGetSymbolAddress((void**)&ep, g_e);
    cudaGetSymbolAddress((void**)&sg, g_sg);

    cudaFuncSetAttribute(attn_mma_kernel,
                         cudaFuncAttributeMaxDynamicSharedMemorySize, ATTN_SMEM);
    cudaFuncSetAttribute(tgemm_kernel,
                         cudaFuncAttributeMaxDynamicSharedMemorySize, GEMM_SMEM);

    // 1) LN1
    ln_kernel<<<Mrows, 256>>>(x, ln1_w, ln1_b, x1);

    // 2) Q and K in ONE launch (grid.z selects weights), then V
    tgemm_kernel<<<dim3(DCc/128, Mrows/128, 2), 256, GEMM_SMEM>>>(
        x1, wq, bq, nullptr, qp, wk, bk, kp, Mrows, DCc, Dd, 0);
    tgemm_kernel<<<dim3(DMm/128, Mrows/128, 1), 256, GEMM_SMEM>>>(
        x1, wv, bv, nullptr, vp, nullptr, nullptr, nullptr, Mrows, DMm, Dd, 0);

    // 3) causal attention (TF32 MMA, cp.async double-buffered)
    attn_mma_kernel<<<dim3(Tt/64, Bq*Hh), 128, ATTN_SMEM>>>(qp, kp, vp, yp);

    // 4) output projection + residual
    tgemm_kernel<<<dim3(Dd/128, Mrows/128, 1), 256, GEMM_SMEM>>>(
        yp, wo, bo, x, xa, nullptr, nullptr, nullptr, Mrows, Dd, DMm, 1);

    // 5) LN2
    ln_kernel<<<Mrows, 256>>>(xa, ln2_w, ln2_b, x2);

    // 6) e = x2@we + be
    tgemm_kernel<<<dim3(DEe/128, Mrows/128, 1), 256, GEMM_SMEM>>>(
        x2, we, be, nullptr, ep, nullptr, nullptr, nullptr, Mrows, DEe, Dd, 0);

    // 7) sg = silu(x2@wg + bg)
    tgemm_kernel<<<dim3(DGg/128, Mrows/128, 1), 256, GEMM_SMEM>>>(
        x2, wg, bg, nullptr, sg, nullptr, nullptr, nullptr, Mrows, DGg, Dd, 2);

    // 8) e = silu(e * sigmoid(sg@wu + bu))   [fused eg epilogue, mode 4]
    tgemm_kernel<<<dim3(DEe/128, Mrows/128, 1), 256, GEMM_SMEM>>>(
        sg, wu, bu, ep, ep, nullptr, nullptr, nullptr, Mrows, DEe, DGg, 4);

    // 9) out = xa + e@wc + bc
    tgemm_kernel<<<dim3(Dd/128, Mrows/128, 1), 256, GEMM_SMEM>>>(
        ep, wc, bc, xa, out, nullptr, nullptr, nullptr, Mrows, Dd, DEe, 1);
}

// round 17
// speedup vs baseline: 1.2407x; 1.0361x over previous
#include <cuda_runtime.h>
#include <cuda_bf16.h>
#include <cstdint>

// ---------------------------------------------------------------------------
// Problem constants
// ---------------------------------------------------------------------------
#define Bq 2
#define Tt 2048
#define Dd 1024
#define DCc 512
#define DMm 1536
#define Hh 16
#define DEe 4096
#define DGg 1024
#define Mrows (Bq * Tt)          // 4096
#define CHD (DCc / Hh)           // 32
#define MHD (DMm / Hh)           // 96

// ---------------------------------------------------------------------------
// Scratch (device globals; cudaMalloc is forbidden)
// ---------------------------------------------------------------------------
__device__ float g_x1[Mrows * Dd];
__device__ float g_q [Mrows * DCc];
__device__ float g_k [Mrows * DCc];
__device__ float g_v [Mrows * DMm];
__device__ float g_y [Mrows * DMm];
__device__ float g_xa[Mrows * Dd];
__device__ float g_x2[Mrows * Dd];
__device__ float g_e [Mrows * DEe];
__device__ float g_sg[Mrows * DGg];

// ---------------------------------------------------------------------------
// helpers
// ---------------------------------------------------------------------------
__device__ __forceinline__ void mma_tf32(float* c, const uint32_t* a, const uint32_t* b) {
    asm volatile(
        "mma.sync.aligned.m16n8k8.row.col.f32.tf32.tf32.f32 "
        "{%0,%1,%2,%3}, {%4,%5,%6,%7}, {%8,%9}, {%0,%1,%2,%3};"
        : "+f"(c[0]), "+f"(c[1]), "+f"(c[2]), "+f"(c[3])
        : "r"(a[0]), "r"(a[1]), "r"(a[2]), "r"(a[3]), "r"(b[0]), "r"(b[1]));
}

__device__ __forceinline__ void cp_async16(void* smem, const void* gmem) {
    uint32_t s = (uint32_t)__cvta_generic_to_shared(smem);
    asm volatile("cp.async.cg.shared.global [%0], [%1], 16;" :: "r"(s), "l"(gmem));
}
__device__ __forceinline__ void cp_commit() {
    asm volatile("cp.async.commit_group;");
}
template <int N>
__device__ __forceinline__ void cp_wait() {
    asm volatile("cp.async.wait_group %0;" :: "n"(N));
}

// ---------------------------------------------------------------------------
// LayerNorm (unchanged)
// ---------------------------------------------------------------------------
__global__ __launch_bounds__(256) void ln_kernel(
    const float* __restrict__ x, const float* __restrict__ w,
    const float* __restrict__ b, float* __restrict__ out)
{
    int row = blockIdx.x;
    int tid = threadIdx.x;
    const float* xr = x + (size_t)row * Dd;
    float4 v = *(const float4*)(xr + tid * 4);
    float s  = v.x + v.y + v.z + v.w;
    float sq = v.x*v.x + v.y*v.y + v.z*v.z + v.w*v.w;
    #pragma unroll
    for (int o = 16; o > 0; o >>= 1) {
        s  += __shfl_xor_sync(0xffffffffu, s,  o);
        sq += __shfl_xor_sync(0xffffffffu, sq, o);
    }
    __shared__ float ss[8], ssq[8];
    int wid = tid >> 5, lid = tid & 31;
    if (lid == 0) { ss[wid] = s; ssq[wid] = sq; }
    __syncthreads();
    s = 0.f; sq = 0.f;
    #pragma unroll
    for (int i = 0; i < 8; i++) { s += ss[i]; sq += ssq[i]; }
    float mu  = s * (1.f / Dd);
    float var = sq * (1.f / Dd) - mu * mu;
    float rs  = rsqrtf(var + 1e-5f);
    float4 wv = *(const float4*)(w + tid * 4);
    float4 bv = *(const float4*)(b + tid * 4);
    float4 o;
    o.x = (v.x - mu) * rs * wv.x + bv.x;
    o.y = (v.y - mu) * rs * wv.y + bv.y;
    o.z = (v.z - mu) * rs * wv.z + bv.z;
    o.w = (v.w - mu) * rs * wv.w + bv.w;
    *(float4*)(out + (size_t)row * Dd + tid * 4) = o;
}

// ---------------------------------------------------------------------------
// TF32 tensor-core GEMM, cp.async 4-stage pipeline (round-16, passed).
// modes: 0 bias, 1 +res, 2 SiLU, 3 sigmoid, 4 fused: C = silu(res*sigmoid(acc+bias))
// gridDim.z == 2 selects (W2, bias2, C2) for blockIdx.z == 1 (same code path).
// ---------------------------------------------------------------------------
#define AST 20
#define BST 136
#define NSTG 4
#define STAGE_F (128 * AST + 16 * BST)            // floats per stage: 4736
#define GEMM_SMEM (NSTG * STAGE_F * 4)            // 75776 bytes

__global__ __launch_bounds__(256) void tgemm_kernel(
    const float* __restrict__ A,
    const float* __restrict__ W,  const float* __restrict__ bias,
    const float* __restrict__ res, float* __restrict__ C,
    const float* __restrict__ W2, const float* __restrict__ bias2,
    float* __restrict__ C2,
    int M, int N, int K, int mode)
{
    extern __shared__ float smf[];
    if (blockIdx.z) { W = W2; bias = bias2; C = C2; }

    int t = threadIdx.x;
    int bm = blockIdx.y * 128;
    int bn = blockIdx.x * 128;
    int lane = t & 31, wid = t >> 5;
    int r = lane >> 2, q = lane & 3;
    int m_base = (wid & 3) * 32;
    int n_base = (wid >> 2) * 64;

    int a_row0 = t >> 2;
    int a_kc   = (t & 3) * 4;
    int b_row0 = t >> 5;
    int b_col  = (t & 31) * 4;

    const int nk = K / 16;

    const float* Abase  = A + (size_t)(bm + a_row0) * K + a_kc;
    const float* Abase2 = Abase + (size_t)64 * K;
    const float* Wbase  = W + (size_t)b_row0 * N + bn + b_col;
    const float* Wbase2 = Wbase + (size_t)8 * N;

    float acc[2][8][4];
    #pragma unroll
    for (int i = 0; i < 2; i++)
        #pragma unroll
        for (int j = 0; j < 8; j++)
            #pragma unroll
            for (int c = 0; c < 4; c++) acc[i][j][c] = 0.f;

    #define STAGE_A(s) (smf + (s) * STAGE_F)
    #define STAGE_B(s) (smf + (s) * STAGE_F + 128 * AST)

    #pragma unroll
    for (int s = 0; s < 3; s++) {
        int k0 = s * 16;
        cp_async16(STAGE_A(s) + a_row0 * AST + a_kc,        Abase  + k0);
        cp_async16(STAGE_A(s) + (a_row0 + 64) * AST + a_kc, Abase2 + k0);
        cp_async16(STAGE_B(s) + b_row0 * BST + b_col,       Wbase  + (size_t)k0 * N);
        cp_async16(STAGE_B(s) + (b_row0 + 8) * BST + b_col, Wbase2 + (size_t)k0 * N);
        cp_commit();
    }
    cp_wait<2>();
    __syncthreads();

    for (int kt = 0; kt < nk; kt++) {
        int buf = kt & 3;
        const float* As = STAGE_A(buf);
        const float* Bs = STAGE_B(buf);

        #pragma unroll
        for (int k8 = 0; k8 < 16; k8 += 8) {
            uint32_t a[2][4], b[8][2];
            #pragma unroll
            for (int mt = 0; mt < 2; mt++) {
                int m0 = m_base + mt * 16;
                a[mt][0] = __float_as_uint(As[(m0 + r    ) * AST + k8 + q]);
                a[mt][1] = __float_as_uint(As[(m0 + r + 8) * AST + k8 + q]);
                a[mt][2] = __float_as_uint(As[(m0 + r    ) * AST + k8 + q + 4]);
                a[mt][3] = __float_as_uint(As[(m0 + r + 8) * AST + k8 + q + 4]);
            }
            #pragma unroll
            for (int nt = 0; nt < 8; nt++) {
                int n0 = n_base + nt * 8;
                b[nt][0] = __float_as_uint(Bs[(k8 + q    ) * BST + n0 + r]);
                b[nt][1] = __float_as_uint(Bs[(k8 + q + 4) * BST + n0 + r]);
            }
            #pragma unroll
            for (int mt = 0; mt < 2; mt++)
                #pragma unroll
                for (int nt = 0; nt < 8; nt++)
                    mma_tf32(acc[mt][nt], a[mt], b[nt]);
        }

        if (kt + 3 < nk) {
            int s  = (kt + 3) & 3;
            int k0 = (kt + 3) * 16;
            cp_async16(STAGE_A(s) + a_row0 * AST + a_kc,        Abase  + k0);
            cp_async16(STAGE_A(s) + (a_row0 + 64) * AST + a_kc, Abase2 + k0);
            cp_async16(STAGE_B(s) + b_row0 * BST + b_col,       Wbase  + (size_t)k0 * N);
            cp_async16(STAGE_B(s) + (b_row0 + 8) * BST + b_col, Wbase2 + (size_t)k0 * N);
        }
        cp_commit();
        cp_wait<2>();
        __syncthreads();
    }

    #pragma unroll
    for (int mt = 0; mt < 2; mt++) {
        int row0 = bm + m_base + mt * 16 + r;
        #pragma unroll
        for (int nt = 0; nt < 8; nt++) {
            int col = bn + n_base + nt * 8 + q * 2;
            float b0 = bias[col], b1 = bias[col + 1];
            float v0 = acc[mt][nt][0] + b0;
            float v1 = acc[mt][nt][1] + b1;
            float v2 = acc[mt][nt][2] + b0;
            float v3 = acc[mt][nt][3] + b1;
            if (mode == 1) {
                v0 += res[(size_t)row0 * N + col];
                v1 += res[(size_t)row0 * N + col + 1];
                v2 += res[(size_t)(row0 + 8) * N + col];
                v3 += res[(size_t)(row0 + 8) * N + col + 1];
            } else if (mode == 2) {
                v0 = v0 / (1.f + __expf(-v0));
                v1 = v1 / (1.f + __expf(-v1));
                v2 = v2 / (1.f + __expf(-v2));
                v3 = v3 / (1.f + __expf(-v3));
            } else if (mode == 3) {
                v0 = 1.f / (1.f + __expf(-v0));
                v1 = 1.f / (1.f + __expf(-v1));
                v2 = 1.f / (1.f + __expf(-v2));
                v3 = 1.f / (1.f + __expf(-v3));
            } else if (mode == 4) {
                float e0 = res[(size_t)row0 * N + col];
                float e1 = res[(size_t)row0 * N + col + 1];
                float e2 = res[(size_t)(row0 + 8) * N + col];
                float e3 = res[(size_t)(row0 + 8) * N + col + 1];
                float t0 = e0 * (1.f / (1.f + __expf(-v0)));
                float t1 = e1 * (1.f / (1.f + __expf(-v1)));
                float t2 = e2 * (1.f / (1.f + __expf(-v2)));
                float t3 = e3 * (1.f / (1.f + __expf(-v3)));
                v0 = t0 / (1.f + __expf(-t0));
                v1 = t1 / (1.f + __expf(-t1));
                v2 = t2 / (1.f + __expf(-t2));
                v3 = t3 / (1.f + __expf(-t3));
            }
            *(float2*)(C + (size_t)row0 * N + col)       = make_float2(v0, v1);
            *(float2*)(C + (size_t)(row0 + 8) * N + col) = make_float2(v2, v3);
        }
    }
}

// ---------------------------------------------------------------------------
// TF32 MMA flash attention, 128 q-rows per CTA (8 warps), cp.async
// double-buffered K/V, V row-major. Each K/V tile feeds 128 q-rows.
// ---------------------------------------------------------------------------
#define AT_KST 36      // K tile stride (floats)
#define AT_VST 104     // V tile stride (floats)
#define AT_SST 68
#define AT_KTILE (64 * AT_KST)     // 2304 floats
#define AT_VTILE (64 * AT_VST)     // 6656 floats
#define ATTN_SMEM ((2*AT_KTILE + 2*AT_VTILE + 8*16*AT_SST) * 4)   // 106496 B

__global__ __launch_bounds__(256) void attn_mma_kernel(
    const float* __restrict__ q, const float* __restrict__ k,
    const float* __restrict__ v, float* __restrict__ y)
{
    extern __shared__ float sm[];
    float* Kb = sm;                        // [2][64][AT_KST]
    float* Vb = sm + 2 * AT_KTILE;         // [2][64][AT_VST]
    float* Ss = Vb + 2 * AT_VTILE;         // [8][16][AT_SST]

    int tid  = threadIdx.x;
    int wid  = tid >> 5, lane = tid & 31;
    int r    = lane >> 2, qd = lane & 3;
    int qt   = (gridDim.x - 1) - blockIdx.x;   // heavy tiles first
    int bh   = blockIdx.y;
    int b    = bh >> 4, h = bh & 15;
    int q0   = qt * 128;
    int mrow = wid * 16;

    const float* qbase = q + (size_t)b * Tt * DCc + h * CHD;
    const float* kbase = k + (size_t)b * Tt * DCc + h * CHD;
    const float* vbase = v + (size_t)b * Tt * DMm + h * MHD;

    const float scale = 0.17677669529663687f;
    int grow0 = q0 + mrow + r;
    uint32_t qa[4][4];
    #pragma unroll
    for (int ks = 0; ks < 4; ks++) {
        qa[ks][0] = __float_as_uint(qbase[(size_t)grow0       * DCc + ks * 8 + qd    ] * scale);
        qa[ks][1] = __float_as_uint(qbase[(size_t)(grow0 + 8) * DCc + ks * 8 + qd    ] * scale);
        qa[ks][2] = __float_as_uint(qbase[(size_t)grow0       * DCc + ks * 8 + qd + 4] * scale);
        qa[ks][3] = __float_as_uint(qbase[(size_t)(grow0 + 8) * DCc + ks * 8 + qd + 4] * scale);
    }

    float m0 = -1e30f, m1 = -1e30f, l0 = 0.f, l1 = 0.f;
    float o[12][4];
    #pragma unroll
    for (int nt = 0; nt < 12; nt++)
        #pragma unroll
        for (int c = 0; c < 4; c++) o[nt][c] = 0.f;

    float* Sw = Ss + wid * 16 * AT_SST;

    // tile loader: pure cp.async, 256 threads (K: 2 chunks/thread; V: 6)
    #define AT_LOAD(bufi, kk)                                                  \
        do {                                                                   \
            float* Kd = Kb + (bufi) * AT_KTILE;                                \
            float* Vd = Vb + (bufi) * AT_VTILE;                                \
            _Pragma("unroll")                                                  \
            for (int i = 0; i < 2; i++) {                                      \
                int c = tid + i * 256;                                         \
                int row = c >> 3, c8 = c & 7;                                  \
                cp_async16(Kd + row * AT_KST + c8 * 4,                         \
                           kbase + (size_t)((kk) + row) * DCc + c8 * 4);       \
            }                                                                  \
            _Pragma("unroll")                                                  \
            for (int i = 0; i < 6; i++) {                                      \
                int c = tid + i * 256;                                         \
                int row = c / 24, c24 = c % 24;                                \
                cp_async16(Vd + row * AT_VST + c24 * 4,                        \
                           vbase + (size_t)((kk) + row) * DMm + c24 * 4);      \
            }                                                                  \
        } while (0)

    const int nj = 2 * qt + 2;   // k-tiles covering rows [0, q0+128)

    // prologue: tile 0 -> buf 0
    AT_LOAD(0, 0);
    cp_commit();

    for (int j = 0; j < nj; j++) {
        int buf = j & 1;
        if (j + 1 < nj) AT_LOAD(buf ^ 1, (j + 1) * 64);
        cp_commit();
        cp_wait<1>();
        __syncthreads();

        const float* Ks = Kb + buf * AT_KTILE;
        const float* Vs = Vb + buf * AT_VTILE;
        int k0 = j * 64;

        // S = Q @ K^T  (16 x 64 per warp)
        float sc[8][4];
        #pragma unroll
        for (int nt = 0; nt < 8; nt++)
            #pragma unroll
            for (int c = 0; c < 4; c++) sc[nt][c] = 0.f;
        #pragma unroll
        for (int ks = 0; ks < 4; ks++) {
            #pragma unroll
            for (int nt = 0; nt < 8; nt++) {
                uint32_t bb[2];
                bb[0] = __float_as_uint(Ks[(nt * 8 + r) * AT_KST + ks * 8 + qd    ]);
                bb[1] = __float_as_uint(Ks[(nt * 8 + r) * AT_KST + ks * 8 + qd + 4]);
                mma_tf32(sc[nt], qa[ks], bb);
            }
        }

        // causal mask + online softmax
        float mx0 = -1e30f, mx1 = -1e30f;
        #pragma unroll
        for (int nt = 0; nt < 8; nt++) {
            int c = k0 + nt * 8 + 2 * qd;
            if (c     > grow0    ) sc[nt][0] = -1e30f;
            if (c + 1 > grow0    ) sc[nt][1] = -1e30f;
            if (c     > grow0 + 8) sc[nt][2] = -1e30f;
            if (c + 1 > grow0 + 8) sc[nt][3] = -1e30f;
            mx0 = fmaxf(mx0, fmaxf(sc[nt][0], sc[nt][1]));
            mx1 = fmaxf(mx1, fmaxf(sc[nt][2], sc[nt][3]));
        }
        mx0 = fmaxf(mx0, __shfl_xor_sync(0xffffffffu, mx0, 1));
        mx0 = fmaxf(mx0, __shfl_xor_sync(0xffffffffu, mx0, 2));
        mx1 = fmaxf(mx1, __shfl_xor_sync(0xffffffffu, mx1, 1));
        mx1 = fmaxf(mx1, __shfl_xor_sync(0xffffffffu, mx1, 2));

        float mn0 = fmaxf(m0, mx0), mn1 = fmaxf(m1, mx1);
        float corr0 = __expf(m0 - mn0), corr1 = __expf(m1 - mn1);
        float s0 = 0.f, s1 = 0.f;
        #pragma unroll
        for (int nt = 0; nt < 8; nt++) {
            float p00 = __expf(sc[nt][0] - mn0);
            float p01 = __expf(sc[nt][1] - mn0);
            float p10 = __expf(sc[nt][2] - mn1);
            float p11 = __expf(sc[nt][3] - mn1);
            s0 += p00 + p01;
            s1 += p10 + p11;
            int cb = nt * 8 + 2 * qd;
            Sw[r * AT_SST + cb]           = p00;
            Sw[r * AT_SST + cb + 1]       = p01;
            Sw[(r + 8) * AT_SST + cb]     = p10;
            Sw[(r + 8) * AT_SST + cb + 1] = p11;
        }
        s0 += __shfl_xor_sync(0xffffffffu, s0, 1);
        s0 += __shfl_xor_sync(0xffffffffu, s0, 2);
        s1 += __shfl_xor_sync(0xffffffffu, s1, 1);
        s1 += __shfl_xor_sync(0xffffffffu, s1, 2);
        l0 = l0 * corr0 + s0;
        l1 = l1 * corr1 + s1;
        m0 = mn0; m1 = mn1;
        #pragma unroll
        for (int nt = 0; nt < 12; nt++) {
            o[nt][0] *= corr0; o[nt][1] *= corr0;
            o[nt][2] *= corr1; o[nt][3] *= corr1;
        }
        __syncwarp();

        // O += P @ V  (V row-major: B fragment from Vs[kv][dim])
        #pragma unroll
        for (int ks = 0; ks < 8; ks++) {
            uint32_t pa[4];
            pa[0] = __float_as_uint(Sw[r       * AT_SST + ks * 8 + qd    ]);
            pa[1] = __float_as_uint(Sw[(r + 8) * AT_SST + ks * 8 + qd    ]);
            pa[2] = __float_as_uint(Sw[r       * AT_SST + ks * 8 + qd + 4]);
            pa[3] = __float_as_uint(Sw[(r + 8) * AT_SST + ks * 8 + qd + 4]);
            #pragma unroll
            for (int nt = 0; nt < 12; nt++) {
                uint32_t bb[2];
                bb[0] = __float_as_uint(Vs[(ks * 8 + qd    ) * AT_VST + nt * 8 + r]);
                bb[1] = __float_as_uint(Vs[(ks * 8 + qd + 4) * AT_VST + nt * 8 + r]);
                mma_tf32(o[nt], pa, bb);
            }
        }
        __syncthreads();   // all warps done with buf before prefetch overwrites it
    }

    float inv0 = 1.f / l0, inv1 = 1.f / l1;
    float* yb = y + (size_t)b * Tt * DMm + h * MHD;
    #pragma unroll
    for (int nt = 0; nt < 12; nt++) {
        int cb = nt * 8 + 2 * qd;
        *(float2*)(yb + (size_t)grow0 * DMm + cb) =
            make_float2(o[nt][0] * inv0, o[nt][1] * inv0);
        *(float2*)(yb + (size_t)(grow0 + 8) * DMm + cb) =
            make_float2(o[nt][2] * inv1, o[nt][3] * inv1);
    }
}

// ---------------------------------------------------------------------------
// Host launcher
// ---------------------------------------------------------------------------
extern "C" void kernel_launch(void* const* d_in, const int* in_sizes, int n_in,
                              void* d_out, int out_size)
{
    const float* x     = (const float*)d_in[0];
    const float* ln1_w = (const float*)d_in[2];
    const float* ln1_b = (const float*)d_in[3];
    const float* wq    = (const float*)d_in[4];
    const float* bq    = (const float*)d_in[5];
    const float* wk    = (const float*)d_in[6];
    const float* bk    = (const float*)d_in[7];
    const float* wv    = (const float*)d_in[8];
    const float* bv    = (const float*)d_in[9];
    const float* wo    = (const float*)d_in[10];
    const float* bo    = (const float*)d_in[11];
    const float* ln2_w = (const float*)d_in[12];
    const float* ln2_b = (const float*)d_in[13];
    const float* we    = (const float*)d_in[14];
    const float* be    = (const float*)d_in[15];
    const float* wg    = (const float*)d_in[16];
    const float* bg    = (const float*)d_in[17];
    const float* wu    = (const float*)d_in[18];
    const float* bu    = (const float*)d_in[19];
    const float* wc    = (const float*)d_in[20];
    const float* bc    = (const float*)d_in[21];
    float* out = (float*)d_out;

    float *x1, *qp, *kp, *vp, *yp, *xa, *x2, *ep, *sg;
    cudaGetSymbolAddress((void**)&x1, g_x1);
    cudaGetSymbolAddress((void**)&qp, g_q);
    cudaGetSymbolAddress((void**)&kp, g_k);
    cudaGetSymbolAddress((void**)&vp, g_v);
    cudaGetSymbolAddress((void**)&yp, g_y);
    cudaGetSymbolAddress((void**)&xa, g_xa);
    cudaGetSymbolAddress((void**)&x2, g_x2);
    cudaGetSymbolAddress((void**)&ep, g_e);
    cudaGetSymbolAddress((void**)&sg, g_sg);

    cudaFuncSetAttribute(attn_mma_kernel,
                         cudaFuncAttributeMaxDynamicSharedMemorySize, ATTN_SMEM);
    cudaFuncSetAttribute(tgemm_kernel,
                         cudaFuncAttributeMaxDynamicSharedMemorySize, GEMM_SMEM);

    // 1) LN1
    ln_kernel<<<Mrows, 256>>>(x, ln1_w, ln1_b, x1);

    // 2) Q and K in ONE launch (grid.z selects weights), then V
    tgemm_kernel<<<dim3(DCc/128, Mrows/128, 2), 256, GEMM_SMEM>>>(
        x1, wq, bq, nullptr, qp, wk, bk, kp, Mrows, DCc, Dd, 0);
    tgemm_kernel<<<dim3(DMm/128, Mrows/128, 1), 256, GEMM_SMEM>>>(
        x1, wv, bv, nullptr, vp, nullptr, nullptr, nullptr, Mrows, DMm, Dd, 0);

    // 3) causal attention (TF32 MMA, 128 q-rows/CTA, double-buffered)
    attn_mma_kernel<<<dim3(Tt/128, Bq*Hh), 256, ATTN_SMEM>>>(qp, kp, vp, yp);

    // 4) output projection + residual
    tgemm_kernel<<<dim3(Dd/128, Mrows/128, 1), 256, GEMM_SMEM>>>(
        yp, wo, bo, x, xa, nullptr, nullptr, nullptr, Mrows, Dd, DMm, 1);

    // 5) LN2
    ln_kernel<<<Mrows, 256>>>(xa, ln2_w, ln2_b, x2);

    // 6) e = x2@we + be
    tgemm_kernel<<<dim3(DEe/128, Mrows/128, 1), 256, GEMM_SMEM>>>(
        x2, we, be, nullptr, ep, nullptr, nullptr, nullptr, Mrows, DEe, Dd, 0);

    // 7) sg = silu(x2@wg + bg)
    tgemm_kernel<<<dim3(DGg/128, Mrows/128, 1), 256, GEMM_SMEM>>>(
        x2, wg, bg, nullptr, sg, nullptr, nullptr, nullptr, Mrows, DGg, Dd, 2);

    // 8) e = silu(e * sigmoid(sg@wu + bu))   [fused eg epilogue, mode 4]
    tgemm_kernel<<<dim3(DEe/128, Mrows/128, 1), 256, GEMM_SMEM>>>(
        sg, wu, bu, ep, ep, nullptr, nullptr, nullptr, Mrows, DEe, DGg, 4);

    // 9) out = xa + e@wc + bc
    tgemm_kernel<<<dim3(Dd/128, Mrows/128, 1), 256, GEMM_SMEM>>>(
        ep, wc, bc, xa, out, nullptr, nullptr, nullptr, Mrows, Dd, DEe, 1);
}